// round 14
// baseline (speedup 1.0000x reference)
#include <cuda_runtime.h>
#include <cuda_fp16.h>
#include <math.h>

// Problem constants (fixed shapes)
#define S_LEN   2048
#define BATCH   4
#define NHEADS  16
#define DKV     64
#define DMODEL  1024
#define M_ROWS  (BATCH * S_LEN)                 // 8192
#define OUT_ELEMS  (M_ROWS * DMODEL)            // 8388608
#define BIAS_ELEMS (NHEADS * S_LEN * S_LEN)     // 67108864

// ---------------------------------------------------------------------------
// Device scratch (fp16 everywhere)
// ---------------------------------------------------------------------------
__device__ __half g_xh[M_ROWS * DMODEL];
__device__ __half g_xl[M_ROWS * DMODEL];
__device__ __half g_wqh[DMODEL * DMODEL];
__device__ __half g_wql[DMODEL * DMODEL];
__device__ __half g_wkh[DMODEL * DMODEL];
__device__ __half g_wkl[DMODEL * DMODEL];
__device__ __half g_wvh[DMODEL * DMODEL];
__device__ __half g_wvl[DMODEL * DMODEL];
__device__ __half g_woh[DMODEL * DMODEL];
__device__ __half g_wol[DMODEL * DMODEL];
__device__ __half g_qh[M_ROWS * DMODEL];
__device__ __half g_ql[M_ROWS * DMODEL];
__device__ __half g_kh[M_ROWS * DMODEL];
__device__ __half g_kl[M_ROWS * DMODEL];
__device__ __half g_vh[M_ROWS * DMODEL];
__device__ __half g_oh[M_ROWS * DMODEL];

// ---------------------------------------------------------------------------
// PTX helpers (sm_80-level only)
// ---------------------------------------------------------------------------
__device__ __forceinline__ unsigned smem_u32(const void* p) {
    unsigned a;
    asm("{ .reg .u64 t; cvta.to.shared.u64 t, %1; cvt.u32.u64 %0, t; }"
        : "=r"(a) : "l"(p));
    return a;
}

#define LDMATRIX_X4(r0, r1, r2, r3, addr)                                      \
    asm volatile("ldmatrix.sync.aligned.m8n8.x4.shared.b16 {%0,%1,%2,%3}, [%4];" \
                 : "=r"(r0), "=r"(r1), "=r"(r2), "=r"(r3) : "r"(addr))

#define LDMATRIX_X4_T(r0, r1, r2, r3, addr)                                    \
    asm volatile("ldmatrix.sync.aligned.m8n8.x4.trans.shared.b16 {%0,%1,%2,%3}, [%4];" \
                 : "=r"(r0), "=r"(r1), "=r"(r2), "=r"(r3) : "r"(addr))

#define MMAF16(d, a0, a1, a2, a3, b0, b1)                                      \
    asm volatile("mma.sync.aligned.m16n8k16.row.col.f32.f16.f16.f32 "          \
                 "{%0,%1,%2,%3},{%4,%5,%6,%7},{%8,%9},{%0,%1,%2,%3};"          \
                 : "+f"((d)[0]), "+f"((d)[1]), "+f"((d)[2]), "+f"((d)[3])      \
                 : "r"(a0), "r"(a1), "r"(a2), "r"(a3), "r"(b0), "r"(b1))

#define CP_ASYNC16(dst, src)                                                   \
    asm volatile("cp.async.cg.shared.global [%0], [%1], 16;"                   \
                 :: "r"(dst), "l"(src) : "memory")
#define CP_COMMIT() asm volatile("cp.async.commit_group;" ::: "memory")
#define CP_WAIT1()  asm volatile("cp.async.wait_group 1;" ::: "memory")
#define CP_WAIT0()  asm volatile("cp.async.wait_group 0;" ::: "memory")

__device__ __forceinline__ unsigned pack2h(float a, float b) {
    __half2 h = __floats2half2_rn(a, b);
    return *reinterpret_cast<unsigned*>(&h);
}

// ---------------------------------------------------------------------------
// Relative-position bucket (exact integer reformulation of the reference)
// ---------------------------------------------------------------------------
__device__ __forceinline__ int rel_bucket(int rel) {
    int ret = (rel > 0) ? 16 : 0;
    int rp  = (rel < 0) ? -rel : rel;
    int off;
    if (rp < 8) {
        off = rp;
    } else {
        off = 8 + (rp >= 12) + (rp >= 16) + (rp >= 23) + (rp >= 32)
                + (rp >= 46) + (rp >= 64) + (rp >= 91);
    }
    return ret + off;
}

// ---------------------------------------------------------------------------
// pos_bias writer (float4 stores) — runs on forked stream
// ---------------------------------------------------------------------------
__global__ __launch_bounds__(256) void bias_kernel(const float* __restrict__ tbl,
                                                   float* __restrict__ outb) {
    __shared__ float tcol[32];
    const int q = blockIdx.x;
    const int h = blockIdx.y;
    if (threadIdx.x < 32) tcol[threadIdx.x] = tbl[threadIdx.x * NHEADS + h];
    __syncthreads();
    float4* row = (float4*)(outb + ((size_t)h * S_LEN + q) * S_LEN);
#pragma unroll
    for (int it = 0; it < 2; it++) {
        int k4 = threadIdx.x + it * 256;
        int k = k4 * 4;
        float4 v = make_float4(tcol[rel_bucket(k - q)],
                               tcol[rel_bucket(k + 1 - q)],
                               tcol[rel_bucket(k + 2 - q)],
                               tcol[rel_bucket(k + 3 - q)]);
        row[k4] = v;
    }
}

// ---------------------------------------------------------------------------
// ALL conversions in one launch
// ---------------------------------------------------------------------------
__global__ __launch_bounds__(256) void conv_all(
    const float* __restrict__ X,  __half* __restrict__ xh,  __half* __restrict__ xl,
    const float* __restrict__ Wq, __half* __restrict__ wqh, __half* __restrict__ wql,
    const float* __restrict__ Wk, __half* __restrict__ wkh, __half* __restrict__ wkl,
    const float* __restrict__ Wv, __half* __restrict__ wvh, __half* __restrict__ wvl,
    const float* __restrict__ Wo, __half* __restrict__ woh, __half* __restrict__ wol) {
    const int tid = threadIdx.x;
    if (blockIdx.x < 8192) {
        int idx = blockIdx.x * 256 + tid;
        float4 v = ((const float4*)X)[idx];
        __half h0 = __float2half_rn(v.x), h1 = __float2half_rn(v.y);
        __half h2 = __float2half_rn(v.z), h3 = __float2half_rn(v.w);
        unsigned* H = (unsigned*)xh;
        unsigned* L = (unsigned*)xl;
        H[idx * 2]     = pack2h(v.x, v.y);
        H[idx * 2 + 1] = pack2h(v.z, v.w);
        L[idx * 2]     = pack2h(v.x - __half2float(h0), v.y - __half2float(h1));
        L[idx * 2 + 1] = pack2h(v.z - __half2float(h2), v.w - __half2float(h3));
        return;
    }
    __shared__ float t[32][33];
    const int wi = blockIdx.x - 8192;
    const float* W;
    __half *Th, *Tl;
    switch (wi >> 10) {
        case 0:  W = Wq; Th = wqh; Tl = wql; break;
        case 1:  W = Wk; Th = wkh; Tl = wkl; break;
        case 2:  W = Wv; Th = wvh; Tl = wvl; break;
        default: W = Wo; Th = woh; Tl = wol; break;
    }
    const int b  = wi & 1023;
    const int nb = (b & 31) * 32, kb = (b >> 5) * 32;
    const int tx = tid & 31, ty = tid >> 5;
#pragma unroll
    for (int r = ty; r < 32; r += 8)
        t[r][tx] = W[(size_t)(kb + r) * DMODEL + nb + tx];
    __syncthreads();
#pragma unroll
    for (int r = ty; r < 32; r += 8) {
        float v = t[tx][r];  // = W[kb+tx][nb+r]
        __half h = __float2half_rn(v);
        Th[(size_t)(nb + r) * DMODEL + kb + tx] = h;
        Tl[(size_t)(nb + r) * DMODEL + kb + tx] =
            __float2half_rn(v - __half2float(h));
    }
}

// ---------------------------------------------------------------------------
// HMMA fp16 GEMM (R8/R10 config — best measured):
//   SPLIT==3: C = AhBh + AhBl + AlBh   SPLIT==1: C = AhBh  (all f32-acc)
//   OUTM: 0 -> float C; 1 -> fp16 hi/lo pair; 2 -> fp16 single
// CTA tile 128x128, BK=32, 4 warps @ 64x64, 2-stage cp.async, 2 CTAs/SM.
// ---------------------------------------------------------------------------
#define ROWB 80                               // 32 fp16 (64B) + 16B pad
#define MATB (128 * ROWB)                     // 10240 B (128 rows)

template<int SPLIT, int OUTM>
__global__ __launch_bounds__(128, 2)
void gemm_h(const __half* __restrict__ Ah, const __half* __restrict__ Al,
            const __half* __restrict__ Bh, const __half* __restrict__ Bl,
            float* __restrict__ Cf, __half* __restrict__ Ch,
            __half* __restrict__ Cl, int M, int N, int K) {
    constexpr int NSP = (SPLIT == 3) ? 2 : 1;
    constexpr int STAGEB = NSP * 2 * MATB;
    constexpr int BOFF = NSP * MATB;
    extern __shared__ char smx[];
    const unsigned sb = smem_u32(smx);
    const int tid  = threadIdx.x;
    const int wid  = tid >> 5;
    const int lane = tid & 31;
    const int m0 = blockIdx.y * 128, n0 = blockIdx.x * 128;
    const int wm = (wid & 1) * 64;
    const int wn = (wid >> 1) * 64;

    const __half* aS[2];
    const __half* bS[2];
    aS[0] = Ah + (size_t)m0 * K;
    bS[0] = Bh + (size_t)n0 * K;
    aS[1] = (SPLIT == 3) ? (Al + (size_t)m0 * K) : aS[0];
    bS[1] = (SPLIT == 3) ? (Bl + (size_t)n0 * K) : bS[0];

    const int ldrow = tid >> 2;
    const int ldch  = tid & 3;

    const unsigned a_off = (unsigned)((lane & 15) * ROWB + (lane >> 4) * 16);
    const unsigned b_off = (unsigned)((((lane >> 4) << 3) + (lane & 7)) * ROWB
                                      + ((lane >> 3) & 1) * 16);

    float acc[4][8][4];
#pragma unroll
    for (int i = 0; i < 4; i++)
#pragma unroll
        for (int j = 0; j < 8; j++)
#pragma unroll
            for (int r = 0; r < 4; r++) acc[i][j][r] = 0.0f;

    const int NIT = K / 32;

    auto load_stage = [&](int s, int kit) {
        const int k0 = kit * 32;
        unsigned db = sb + (unsigned)(s * STAGEB);
#pragma unroll
        for (int sp = 0; sp < NSP; sp++) {
#pragma unroll
            for (int i = 0; i < 4; i++) {
                int row = ldrow + i * 32;
                CP_ASYNC16(db + (unsigned)(sp * MATB + row * ROWB + ldch * 16),
                           aS[sp] + k0 + (size_t)row * K + ldch * 8);
            }
#pragma unroll
            for (int i = 0; i < 4; i++) {
                int row = ldrow + i * 32;
                CP_ASYNC16(db + (unsigned)(BOFF + sp * MATB + row * ROWB + ldch * 16),
                           bS[sp] + k0 + (size_t)row * K + ldch * 8);
            }
        }
    };

    load_stage(0, 0);
    CP_COMMIT();

    for (int kit = 0; kit < NIT; kit++) {
        if (kit + 1 < NIT) {
            load_stage((kit + 1) & 1, kit + 1);
            CP_COMMIT();
            CP_WAIT1();
        } else {
            CP_WAIT0();
        }
        __syncthreads();

        const unsigned tb = sb + (unsigned)((kit & 1) * STAGEB);
#pragma unroll
        for (int kk = 0; kk < 32; kk += 16) {
            unsigned afr[NSP][4][4];
            unsigned bfr[NSP][4][4];
#pragma unroll
            for (int sp = 0; sp < NSP; sp++) {
#pragma unroll
                for (int mt = 0; mt < 4; mt++) {
                    unsigned ad = tb + (unsigned)(sp * MATB) + a_off
                                + (unsigned)((wm + mt * 16) * ROWB + kk * 2);
                    LDMATRIX_X4(afr[sp][mt][0], afr[sp][mt][1],
                                afr[sp][mt][2], afr[sp][mt][3], ad);
                }
#pragma unroll
                for (int nt = 0; nt < 4; nt++) {
                    unsigned bd = tb + (unsigned)(BOFF + sp * MATB) + b_off
                                + (unsigned)((wn + nt * 16) * ROWB + kk * 2);
                    LDMATRIX_X4(bfr[sp][nt][0], bfr[sp][nt][1],
                                bfr[sp][nt][2], bfr[sp][nt][3], bd);
                }
            }
#pragma unroll
            for (int mt = 0; mt < 4; mt++)
#pragma unroll
                for (int n8 = 0; n8 < 8; n8++)
                    MMAF16(acc[mt][n8], afr[0][mt][0], afr[0][mt][1],
                           afr[0][mt][2], afr[0][mt][3],
                           bfr[0][n8 >> 1][(n8 & 1) * 2],
                           bfr[0][n8 >> 1][(n8 & 1) * 2 + 1]);
            if (SPLIT == 3) {
#pragma unroll
                for (int mt = 0; mt < 4; mt++)
#pragma unroll
                    for (int n8 = 0; n8 < 8; n8++)
                        MMAF16(acc[mt][n8], afr[0][mt][0], afr[0][mt][1],
                               afr[0][mt][2], afr[0][mt][3],
                               bfr[1][n8 >> 1][(n8 & 1) * 2],
                               bfr[1][n8 >> 1][(n8 & 1) * 2 + 1]);
#pragma unroll
                for (int mt = 0; mt < 4; mt++)
#pragma unroll
                    for (int n8 = 0; n8 < 8; n8++)
                        MMAF16(acc[mt][n8], afr[1][mt][0], afr[1][mt][1],
                               afr[1][mt][2], afr[1][mt][3],
                               bfr[0][n8 >> 1][(n8 & 1) * 2],
                               bfr[0][n8 >> 1][(n8 & 1) * 2 + 1]);
            }
        }
        __syncthreads();
    }

    // ---- epilogue ----
    const int r0 = lane >> 2, c0 = (lane & 3) * 2;
#pragma unroll
    for (int mt = 0; mt < 4; mt++) {
#pragma unroll
        for (int n8 = 0; n8 < 8; n8++) {
            int row = m0 + wm + mt * 16 + r0;
            int col = n0 + wn + n8 * 8 + c0;
            float v0 = acc[mt][n8][0], v1 = acc[mt][n8][1];
            float v2 = acc[mt][n8][2], v3 = acc[mt][n8][3];
            if (OUTM == 0) {
                float* Cp = Cf + (size_t)row * N + col;
                *(float2*)Cp = make_float2(v0, v1);
                *(float2*)(Cp + (size_t)8 * N) = make_float2(v2, v3);
            } else if (OUTM == 2) {
                *(unsigned*)(Ch + (size_t)row * N + col) = pack2h(v0, v1);
                *(unsigned*)(Ch + (size_t)(row + 8) * N + col) = pack2h(v2, v3);
            } else {
                __half h0 = __float2half_rn(v0), h1 = __float2half_rn(v1);
                __half h2 = __float2half_rn(v2), h3 = __float2half_rn(v3);
                *(unsigned*)(Ch + (size_t)row * N + col) =
                    *(unsigned*)&h0 | (*(unsigned*)&h1 << 16);
                *(unsigned*)(Ch + (size_t)(row + 8) * N + col) =
                    *(unsigned*)&h2 | (*(unsigned*)&h3 << 16);
                *(unsigned*)(Cl + (size_t)row * N + col) =
                    pack2h(v0 - __half2float(h0), v1 - __half2float(h1));
                *(unsigned*)(Cl + (size_t)(row + 8) * N + col) =
                    pack2h(v2 - __half2float(h2), v3 - __half2float(h3));
            }
        }
    }
}

// ---------------------------------------------------------------------------
// HMMA flash attention (R10 version — f32-acc everywhere).
// 128q x 128k tiles, 8 warps; QK split-fp16 (3 MMAs), PV single fp16.
// bbase selects the batch range (split launch for O-projection overlap).
// ---------------------------------------------------------------------------
#define FPITCH 144
#define FMAT (128 * FPITCH)                   // 18432
#define FSTAGE (3 * FMAT)                     // Kh, Kl, V
#define FQOFF (2 * FSTAGE)                    // 110592
#define FLASH_SMEM (FQOFF + 2 * FMAT)         // 147456

__device__ __forceinline__ void load_tile_f(unsigned sdst, const __half* g, int tid) {
#pragma unroll
    for (int i = 0; i < 4; i++) {
        int c = tid + i * 256;
        int row = c >> 3, ch = c & 7;
        CP_ASYNC16(sdst + (unsigned)(row * FPITCH + ch * 16),
                   g + (size_t)row * DMODEL + ch * 8);
    }
}

__global__ __launch_bounds__(256, 1)
void flash_hmma(const __half* __restrict__ Qh, const __half* __restrict__ Ql,
                const __half* __restrict__ Kh, const __half* __restrict__ Kl,
                const __half* __restrict__ Vf, const float* __restrict__ tbl,
                __half* __restrict__ Oh, int bbase) {
    extern __shared__ char sm[];
    __shared__ float tcol[32];
    __shared__ float bias183[184];
    const unsigned sb = smem_u32(sm);
    const int tid = threadIdx.x, wid = tid >> 5, lane = tid & 31;
    const int q0 = blockIdx.x * 128, h = blockIdx.y, b = blockIdx.z + bbase;

    const size_t qbase = ((size_t)(b * S_LEN + q0)) * DMODEL + h * DKV;
    const size_t kbase = ((size_t)(b * S_LEN)) * DMODEL + h * DKV;

    load_tile_f(sb + FQOFF, Qh + qbase, tid);
    load_tile_f(sb + FQOFF + FMAT, Ql + qbase, tid);
    load_tile_f(sb, Kh + kbase, tid);
    load_tile_f(sb + FMAT, Kl + kbase, tid);
    load_tile_f(sb + 2 * FMAT, Vf + kbase, tid);
    CP_COMMIT();

    if (tid < 32) tcol[tid] = tbl[tid * NHEADS + h];
    __syncthreads();
    if (tid < 183) bias183[tid] = tcol[rel_bucket(tid - 91)];

    const int u = lane & 3, g = lane >> 2;
    const int qA = q0 + wid * 16 + g;
    const int qB = qA + 8;

    const unsigned aoff = (unsigned)((lane & 15) * FPITCH + (lane >> 4) * 16);
    const unsigned boff = (unsigned)(((((lane >> 4) << 3) | (lane & 7)) * FPITCH)
                                     + ((lane >> 3) & 1) * 16);
    const unsigned voff = (unsigned)(((((lane >> 3) & 1) * 8 + (lane & 7)) * FPITCH)
                                     + (lane >> 4) * 16);

    unsigned aqh[4][4], aql[4][4];
    float accO[8][4];
#pragma unroll
    for (int i = 0; i < 8; i++)
#pragma unroll
        for (int j = 0; j < 4; j++) accO[i][j] = 0.0f;
    float mA = -1e30f, mB = -1e30f, lA = 0.0f, lB = 0.0f;

    for (int t = 0; t < 16; t++) {
        if (t + 1 < 16) {
            unsigned st = sb + (unsigned)(((t + 1) & 1) * FSTAGE);
            size_t kb2 = kbase + (size_t)(t + 1) * 128 * DMODEL;
            load_tile_f(st, Kh + kb2, tid);
            load_tile_f(st + FMAT, Kl + kb2, tid);
            load_tile_f(st + 2 * FMAT, Vf + kb2, tid);
            CP_COMMIT();
            CP_WAIT1();
        } else {
            CP_WAIT0();
        }
        __syncthreads();

        if (t == 0) {
#pragma unroll
            for (int c = 0; c < 4; c++) {
                unsigned qa = sb + FQOFF + (unsigned)(wid * 16 * FPITCH) + aoff
                            + (unsigned)(c * 32);
                LDMATRIX_X4(aqh[c][0], aqh[c][1], aqh[c][2], aqh[c][3], qa);
                LDMATRIX_X4(aql[c][0], aql[c][1], aql[c][2], aql[c][3], qa + FMAT);
            }
        }

        const unsigned stg = sb + (unsigned)((t & 1) * FSTAGE);

        float accS[16][4];
#pragma unroll
        for (int i = 0; i < 16; i++)
#pragma unroll
            for (int j = 0; j < 4; j++) accS[i][j] = 0.0f;

#pragma unroll
        for (int c = 0; c < 4; c++) {
#pragma unroll
            for (int gp = 0; gp < 4; gp++) {
                unsigned bh[8], bl[8];
#pragma unroll
                for (int e = 0; e < 2; e++) {
                    unsigned ka = stg + boff
                                + (unsigned)((gp * 2 + e) * 16 * FPITCH + c * 32);
                    LDMATRIX_X4(bh[e * 4], bh[e * 4 + 1], bh[e * 4 + 2], bh[e * 4 + 3], ka);
                    LDMATRIX_X4(bl[e * 4], bl[e * 4 + 1], bl[e * 4 + 2], bl[e * 4 + 3],
                                ka + (unsigned)FMAT);
                }
                float* s0 = accS[4 * gp];
                float* s1 = accS[4 * gp + 1];
                float* s2 = accS[4 * gp + 2];
                float* s3 = accS[4 * gp + 3];
                MMAF16(s0, aqh[c][0], aqh[c][1], aqh[c][2], aqh[c][3], bh[0], bh[1]);
                MMAF16(s1, aqh[c][0], aqh[c][1], aqh[c][2], aqh[c][3], bh[2], bh[3]);
                MMAF16(s2, aqh[c][0], aqh[c][1], aqh[c][2], aqh[c][3], bh[4], bh[5]);
                MMAF16(s3, aqh[c][0], aqh[c][1], aqh[c][2], aqh[c][3], bh[6], bh[7]);
                MMAF16(s0, aqh[c][0], aqh[c][1], aqh[c][2], aqh[c][3], bl[0], bl[1]);
                MMAF16(s1, aqh[c][0], aqh[c][1], aqh[c][2], aqh[c][3], bl[2], bl[3]);
                MMAF16(s2, aqh[c][0], aqh[c][1], aqh[c][2], aqh[c][3], bl[4], bl[5]);
                MMAF16(s3, aqh[c][0], aqh[c][1], aqh[c][2], aqh[c][3], bl[6], bl[7]);
                MMAF16(s0, aql[c][0], aql[c][1], aql[c][2], aql[c][3], bh[0], bh[1]);
                MMAF16(s1, aql[c][0], aql[c][1], aql[c][2], aql[c][3], bh[2], bh[3]);
                MMAF16(s2, aql[c][0], aql[c][1], aql[c][2], aql[c][3], bh[4], bh[5]);
                MMAF16(s3, aql[c][0], aql[c][1], aql[c][2], aql[c][3], bh[6], bh[7]);
            }
        }

        const int k0 = t * 128;
        float tmA = -1e30f, tmB = -1e30f;
#pragma unroll
        for (int s8 = 0; s8 < 16; s8++) {
            int kc = k0 + s8 * 8 + 2 * u;
            int iA0 = min(max(kc - qA, -91), 91) + 91;
            int iA1 = min(max(kc + 1 - qA, -91), 91) + 91;
            int iB0 = min(max(kc - qB, -91), 91) + 91;
            int iB1 = min(max(kc + 1 - qB, -91), 91) + 91;
            accS[s8][0] += bias183[iA0];
            accS[s8][1] += bias183[iA1];
            accS[s8][2] += bias183[iB0];
            accS[s8][3] += bias183[iB1];
            tmA = fmaxf(tmA, fmaxf(accS[s8][0], accS[s8][1]));
            tmB = fmaxf(tmB, fmaxf(accS[s8][2], accS[s8][3]));
        }
        tmA = fmaxf(tmA, __shfl_xor_sync(0xffffffffu, tmA, 1));
        tmA = fmaxf(tmA, __shfl_xor_sync(0xffffffffu, tmA, 2));
        tmB = fmaxf(tmB, __shfl_xor_sync(0xffffffffu, tmB, 1));
        tmB = fmaxf(tmB, __shfl_xor_sync(0xffffffffu, tmB, 2));

        float nmA = fmaxf(mA, tmA), scA = __expf(mA - nmA);
        float nmB = fmaxf(mB, tmB), scB = __expf(mB - nmB);
        mA = nmA; mB = nmB;

        float sA = 0.0f, sB = 0.0f;
#pragma unroll
        for (int s8 = 0; s8 < 16; s8++) {
            accS[s8][0] = __expf(accS[s8][0] - nmA);
            accS[s8][1] = __expf(accS[s8][1] - nmA);
            accS[s8][2] = __expf(accS[s8][2] - nmB);
            accS[s8][3] = __expf(accS[s8][3] - nmB);
            sA += accS[s8][0] + accS[s8][1];
            sB += accS[s8][2] + accS[s8][3];
        }
        sA += __shfl_xor_sync(0xffffffffu, sA, 1);
        sA += __shfl_xor_sync(0xffffffffu, sA, 2);
        sB += __shfl_xor_sync(0xffffffffu, sB, 1);
        sB += __shfl_xor_sync(0xffffffffu, sB, 2);
        lA = lA * scA + sA;
        lB = lB * scB + sB;

#pragma unroll
        for (int nt = 0; nt < 8; nt++) {
            accO[nt][0] *= scA; accO[nt][1] *= scA;
            accO[nt][2] *= scB; accO[nt][3] *= scB;
        }

#pragma unroll
        for (int j = 0; j < 8; j++) {
            unsigned a0 = pack2h(accS[2 * j][0], accS[2 * j][1]);
            unsigned a1 = pack2h(accS[2 * j][2], accS[2 * j][3]);
            unsigned a2 = pack2h(accS[2 * j + 1][0], accS[2 * j + 1][1]);
            unsigned a3 = pack2h(accS[2 * j + 1][2], accS[2 * j + 1][3]);
#pragma unroll
            for (int g2 = 0; g2 < 4; g2++) {
                unsigned bv0, bv1, bv2, bv3;
                unsigned va = stg + (unsigned)(2 * FMAT) + voff
                            + (unsigned)(j * 16 * FPITCH + g2 * 32);
                LDMATRIX_X4_T(bv0, bv1, bv2, bv3, va);
                MMAF16(accO[2 * g2], a0, a1, a2, a3, bv0, bv1);
                MMAF16(accO[2 * g2 + 1], a0, a1, a2, a3, bv2, bv3);
            }
        }
        __syncthreads();
    }

    const float iA = 1.0f / lA, iB = 1.0f / lB;
    const size_t rowA = (size_t)(b * S_LEN + qA) * DMODEL + h * DKV;
    const size_t rowB = (size_t)(b * S_LEN + qB) * DMODEL + h * DKV;
#pragma unroll
    for (int nt = 0; nt < 8; nt++) {
        int col = nt * 8 + 2 * u;
        *(unsigned*)(Oh + rowA + col) = pack2h(accO[nt][0] * iA, accO[nt][1] * iA);
        *(unsigned*)(Oh + rowB + col) = pack2h(accO[nt][2] * iB, accO[nt][3] * iB);
    }
}

// ---------------------------------------------------------------------------
extern "C" void kernel_launch(void* const* d_in, const int* in_sizes, int n_in,
                              void* d_out, int out_size) {
    const float* X   = (const float*)d_in[0];
    const float* Wq  = (const float*)d_in[1];
    const float* Wk  = (const float*)d_in[2];
    const float* Wv  = (const float*)d_in[3];
    const float* Wo  = (const float*)d_in[4];
    const float* tbl = (const float*)d_in[5];
    float* out = (float*)d_out;

    __half *xh, *xl, *wqh, *wql, *wkh, *wkl, *wvh, *wvl, *woh, *wol;
    __half *qh, *ql, *kh, *kl, *vh, *oh;
    cudaGetSymbolAddress((void**)&xh, g_xh);
    cudaGetSymbolAddress((void**)&xl, g_xl);
    cudaGetSymbolAddress((void**)&wqh, g_wqh);
    cudaGetSymbolAddress((void**)&wql, g_wql);
    cudaGetSymbolAddress((void**)&wkh, g_wkh);
    cudaGetSymbolAddress((void**)&wkl, g_wkl);
    cudaGetSymbolAddress((void**)&wvh, g_wvh);
    cudaGetSymbolAddress((void**)&wvl, g_wvl);
    cudaGetSymbolAddress((void**)&woh, g_woh);
    cudaGetSymbolAddress((void**)&wol, g_wol);
    cudaGetSymbolAddress((void**)&qh, g_qh);
    cudaGetSymbolAddress((void**)&ql, g_ql);
    cudaGetSymbolAddress((void**)&kh, g_kh);
    cudaGetSymbolAddress((void**)&kl, g_kl);
    cudaGetSymbolAddress((void**)&vh, g_vh);
    cudaGetSymbolAddress((void**)&oh, g_oh);

    static cudaStream_t s2 = nullptr, s3 = nullptr, s4 = nullptr;
    static cudaEvent_t evFork = nullptr, evJoin = nullptr;
    static cudaEvent_t evConv = nullptr, evK = nullptr, evV = nullptr;
    static cudaEvent_t evQ = nullptr, evO2 = nullptr;
    if (s2 == nullptr) {
        cudaStreamCreateWithFlags(&s2, cudaStreamNonBlocking);
        cudaStreamCreateWithFlags(&s3, cudaStreamNonBlocking);
        cudaStreamCreateWithFlags(&s4, cudaStreamNonBlocking);
        cudaEventCreateWithFlags(&evFork, cudaEventDisableTiming);
        cudaEventCreateWithFlags(&evJoin, cudaEventDisableTiming);
        cudaEventCreateWithFlags(&evConv, cudaEventDisableTiming);
        cudaEventCreateWithFlags(&evK, cudaEventDisableTiming);
        cudaEventCreateWithFlags(&evV, cudaEventDisableTiming);
        cudaEventCreateWithFlags(&evQ, cudaEventDisableTiming);
        cudaEventCreateWithFlags(&evO2, cudaEventDisableTiming);
    }

    // ---- fork: pos_bias on side stream ----
    cudaEventRecord(evFork, 0);
    cudaStreamWaitEvent(s2, evFork, 0);
    {
        dim3 bg(S_LEN, NHEADS);
        bias_kernel<<<bg, 256, 0, s2>>>(tbl, out + OUT_ELEMS);
    }
    cudaEventRecord(evJoin, s2);

    // ---- conversions (main stream) ----
    conv_all<<<12288, 256>>>(X, xh, xl, Wq, wqh, wql, Wk, wkh, wkl,
                             Wv, wvh, wvl, Wo, woh, wol);
    cudaEventRecord(evConv, 0);
    cudaStreamWaitEvent(s3, evConv, 0);
    cudaStreamWaitEvent(s4, evConv, 0);

    dim3 gg(DMODEL / 128, M_ROWS / 128);      // (8, 64) = 512 CTAs

    cudaFuncSetAttribute(gemm_h<3, 1>, cudaFuncAttributeMaxDynamicSharedMemorySize,
                         2 * 4 * MATB);
    cudaFuncSetAttribute(gemm_h<1, 2>, cudaFuncAttributeMaxDynamicSharedMemorySize,
                         2 * 2 * MATB);
    cudaFuncSetAttribute(gemm_h<1, 0>, cudaFuncAttributeMaxDynamicSharedMemorySize,
                         2 * 2 * MATB);
    cudaFuncSetAttribute(flash_hmma, cudaFuncAttributeMaxDynamicSharedMemorySize,
                         FLASH_SMEM);

    // Q on main, K on s3, V on s4 — independent, tails overlap
    gemm_h<3, 1><<<gg, 128, 2 * 4 * MATB>>>(xh, xl, wqh, wql,
                                            nullptr, qh, ql,
                                            M_ROWS, DMODEL, DMODEL);
    cudaEventRecord(evQ, 0);
    gemm_h<3, 1><<<gg, 128, 2 * 4 * MATB, s3>>>(xh, xl, wkh, wkl,
                                                nullptr, kh, kl,
                                                M_ROWS, DMODEL, DMODEL);
    cudaEventRecord(evK, s3);
    gemm_h<1, 2><<<gg, 128, 2 * 2 * MATB, s4>>>(xh, nullptr, wvh, nullptr,
                                                nullptr, vh, nullptr,
                                                M_ROWS, DMODEL, DMODEL);
    cudaEventRecord(evV, s4);

    // flash half 1 (b=0,1) on main; flash half 2 (b=2,3) on s3
    cudaStreamWaitEvent(0, evK, 0);
    cudaStreamWaitEvent(0, evV, 0);
    cudaStreamWaitEvent(s3, evQ, 0);
    cudaStreamWaitEvent(s3, evV, 0);

    dim3 fgh(S_LEN / 128, NHEADS, BATCH / 2);
    flash_hmma<<<fgh, 256, FLASH_SMEM>>>(qh, ql, kh, kl, vh, tbl, oh, 0);
    flash_hmma<<<fgh, 256, FLASH_SMEM, s3>>>(qh, ql, kh, kl, vh, tbl, oh, 2);

    // O-projection split by M halves: O1 (rows of b=0,1) overlaps flash half 2
    dim3 ggh(DMODEL / 128, M_ROWS / 2 / 128);   // (8, 32) = 256 CTAs
    const int MH = M_ROWS / 2;
    gemm_h<1, 0><<<ggh, 128, 2 * 2 * MATB>>>(oh, nullptr, woh, nullptr,
                                             out, nullptr, nullptr,
                                             MH, DMODEL, DMODEL);
    gemm_h<1, 0><<<ggh, 128, 2 * 2 * MATB, s3>>>(oh + (size_t)MH * DMODEL, nullptr,
                                                 woh, nullptr,
                                                 out + (size_t)MH * DMODEL,
                                                 nullptr, nullptr,
                                                 MH, DMODEL, DMODEL);
    cudaEventRecord(evO2, s3);
    cudaStreamWaitEvent(0, evO2, 0);

    // ---- join: pos_bias must complete before kernel_launch's work is done ----
    cudaStreamWaitEvent(0, evJoin, 0);
}

// round 15
// speedup vs baseline: 1.5421x; 1.5421x over previous
#include <cuda_runtime.h>
#include <cuda_fp16.h>
#include <math.h>

// Problem constants (fixed shapes)
#define S_LEN   2048
#define BATCH   4
#define NHEADS  16
#define DKV     64
#define DMODEL  1024
#define M_ROWS  (BATCH * S_LEN)                 // 8192
#define OUT_ELEMS  (M_ROWS * DMODEL)            // 8388608
#define BIAS_ELEMS (NHEADS * S_LEN * S_LEN)     // 67108864

// ---------------------------------------------------------------------------
// Device scratch (fp16 everywhere)
// ---------------------------------------------------------------------------
__device__ __half g_xh[M_ROWS * DMODEL];
__device__ __half g_xl[M_ROWS * DMODEL];
__device__ __half g_wqh[DMODEL * DMODEL];
__device__ __half g_wql[DMODEL * DMODEL];
__device__ __half g_wkh[DMODEL * DMODEL];
__device__ __half g_wkl[DMODEL * DMODEL];
__device__ __half g_wvh[DMODEL * DMODEL];
__device__ __half g_wvl[DMODEL * DMODEL];
__device__ __half g_woh[DMODEL * DMODEL];
__device__ __half g_wol[DMODEL * DMODEL];
__device__ __half g_qh[M_ROWS * DMODEL];
__device__ __half g_ql[M_ROWS * DMODEL];
__device__ __half g_kh[M_ROWS * DMODEL];
__device__ __half g_kl[M_ROWS * DMODEL];
__device__ __half g_vh[M_ROWS * DMODEL];
__device__ __half g_oh[M_ROWS * DMODEL];

// ---------------------------------------------------------------------------
// PTX helpers (sm_80-level only)
// ---------------------------------------------------------------------------
__device__ __forceinline__ unsigned smem_u32(const void* p) {
    unsigned a;
    asm("{ .reg .u64 t; cvta.to.shared.u64 t, %1; cvt.u32.u64 %0, t; }"
        : "=r"(a) : "l"(p));
    return a;
}

#define LDMATRIX_X4(r0, r1, r2, r3, addr)                                      \
    asm volatile("ldmatrix.sync.aligned.m8n8.x4.shared.b16 {%0,%1,%2,%3}, [%4];" \
                 : "=r"(r0), "=r"(r1), "=r"(r2), "=r"(r3) : "r"(addr))

#define LDMATRIX_X4_T(r0, r1, r2, r3, addr)                                    \
    asm volatile("ldmatrix.sync.aligned.m8n8.x4.trans.shared.b16 {%0,%1,%2,%3}, [%4];" \
                 : "=r"(r0), "=r"(r1), "=r"(r2), "=r"(r3) : "r"(addr))

#define MMAF16(d, a0, a1, a2, a3, b0, b1)                                      \
    asm volatile("mma.sync.aligned.m16n8k16.row.col.f32.f16.f16.f32 "          \
                 "{%0,%1,%2,%3},{%4,%5,%6,%7},{%8,%9},{%0,%1,%2,%3};"          \
                 : "+f"((d)[0]), "+f"((d)[1]), "+f"((d)[2]), "+f"((d)[3])      \
                 : "r"(a0), "r"(a1), "r"(a2), "r"(a3), "r"(b0), "r"(b1))

#define CP_ASYNC16(dst, src)                                                   \
    asm volatile("cp.async.cg.shared.global [%0], [%1], 16;"                   \
                 :: "r"(dst), "l"(src) : "memory")
#define CP_COMMIT() asm volatile("cp.async.commit_group;" ::: "memory")
#define CP_WAIT1()  asm volatile("cp.async.wait_group 1;" ::: "memory")
#define CP_WAIT0()  asm volatile("cp.async.wait_group 0;" ::: "memory")

__device__ __forceinline__ unsigned pack2h(float a, float b) {
    __half2 h = __floats2half2_rn(a, b);
    return *reinterpret_cast<unsigned*>(&h);
}

// ---------------------------------------------------------------------------
// Relative-position bucket (exact integer reformulation of the reference)
// ---------------------------------------------------------------------------
__device__ __forceinline__ int rel_bucket(int rel) {
    int ret = (rel > 0) ? 16 : 0;
    int rp  = (rel < 0) ? -rel : rel;
    int off;
    if (rp < 8) {
        off = rp;
    } else {
        off = 8 + (rp >= 12) + (rp >= 16) + (rp >= 23) + (rp >= 32)
                + (rp >= 46) + (rp >= 64) + (rp >= 91);
    }
    return ret + off;
}

// ---------------------------------------------------------------------------
// pos_bias writer (float4 stores) — runs on forked stream
// ---------------------------------------------------------------------------
__global__ __launch_bounds__(256) void bias_kernel(const float* __restrict__ tbl,
                                                   float* __restrict__ outb) {
    __shared__ float tcol[32];
    const int q = blockIdx.x;
    const int h = blockIdx.y;
    if (threadIdx.x < 32) tcol[threadIdx.x] = tbl[threadIdx.x * NHEADS + h];
    __syncthreads();
    float4* row = (float4*)(outb + ((size_t)h * S_LEN + q) * S_LEN);
#pragma unroll
    for (int it = 0; it < 2; it++) {
        int k4 = threadIdx.x + it * 256;
        int k = k4 * 4;
        float4 v = make_float4(tcol[rel_bucket(k - q)],
                               tcol[rel_bucket(k + 1 - q)],
                               tcol[rel_bucket(k + 2 - q)],
                               tcol[rel_bucket(k + 3 - q)]);
        row[k4] = v;
    }
}

// ---------------------------------------------------------------------------
// ALL conversions in one launch
// ---------------------------------------------------------------------------
__global__ __launch_bounds__(256) void conv_all(
    const float* __restrict__ X,  __half* __restrict__ xh,  __half* __restrict__ xl,
    const float* __restrict__ Wq, __half* __restrict__ wqh, __half* __restrict__ wql,
    const float* __restrict__ Wk, __half* __restrict__ wkh, __half* __restrict__ wkl,
    const float* __restrict__ Wv, __half* __restrict__ wvh, __half* __restrict__ wvl,
    const float* __restrict__ Wo, __half* __restrict__ woh, __half* __restrict__ wol) {
    const int tid = threadIdx.x;
    if (blockIdx.x < 8192) {
        int idx = blockIdx.x * 256 + tid;
        float4 v = ((const float4*)X)[idx];
        __half h0 = __float2half_rn(v.x), h1 = __float2half_rn(v.y);
        __half h2 = __float2half_rn(v.z), h3 = __float2half_rn(v.w);
        unsigned* H = (unsigned*)xh;
        unsigned* L = (unsigned*)xl;
        H[idx * 2]     = pack2h(v.x, v.y);
        H[idx * 2 + 1] = pack2h(v.z, v.w);
        L[idx * 2]     = pack2h(v.x - __half2float(h0), v.y - __half2float(h1));
        L[idx * 2 + 1] = pack2h(v.z - __half2float(h2), v.w - __half2float(h3));
        return;
    }
    __shared__ float t[32][33];
    const int wi = blockIdx.x - 8192;
    const float* W;
    __half *Th, *Tl;
    switch (wi >> 10) {
        case 0:  W = Wq; Th = wqh; Tl = wql; break;
        case 1:  W = Wk; Th = wkh; Tl = wkl; break;
        case 2:  W = Wv; Th = wvh; Tl = wvl; break;
        default: W = Wo; Th = woh; Tl = wol; break;
    }
    const int b  = wi & 1023;
    const int nb = (b & 31) * 32, kb = (b >> 5) * 32;
    const int tx = tid & 31, ty = tid >> 5;
#pragma unroll
    for (int r = ty; r < 32; r += 8)
        t[r][tx] = W[(size_t)(kb + r) * DMODEL + nb + tx];
    __syncthreads();
#pragma unroll
    for (int r = ty; r < 32; r += 8) {
        float v = t[tx][r];  // = W[kb+tx][nb+r]
        __half h = __float2half_rn(v);
        Th[(size_t)(nb + r) * DMODEL + kb + tx] = h;
        Tl[(size_t)(nb + r) * DMODEL + kb + tx] =
            __float2half_rn(v - __half2float(h));
    }
}

// ---------------------------------------------------------------------------
// HMMA fp16 GEMM (R8/R10 config — best measured):
//   SPLIT==3: C = AhBh + AhBl + AlBh   SPLIT==1: C = AhBh  (all f32-acc)
//   OUTM: 0 -> float C; 1 -> fp16 hi/lo pair; 2 -> fp16 single
// CTA tile 128x128, BK=32, 4 warps @ 64x64, 2-stage cp.async, 2 CTAs/SM.
// ---------------------------------------------------------------------------
#define ROWB 80                               // 32 fp16 (64B) + 16B pad
#define MATB (128 * ROWB)                     // 10240 B (128 rows)

template<int SPLIT, int OUTM>
__global__ __launch_bounds__(128, 2)
void gemm_h(const __half* __restrict__ Ah, const __half* __restrict__ Al,
            const __half* __restrict__ Bh, const __half* __restrict__ Bl,
            float* __restrict__ Cf, __half* __restrict__ Ch,
            __half* __restrict__ Cl, int M, int N, int K) {
    constexpr int NSP = (SPLIT == 3) ? 2 : 1;
    constexpr int STAGEB = NSP * 2 * MATB;
    constexpr int BOFF = NSP * MATB;
    extern __shared__ char smx[];
    const unsigned sb = smem_u32(smx);
    const int tid  = threadIdx.x;
    const int wid  = tid >> 5;
    const int lane = tid & 31;
    const int m0 = blockIdx.y * 128, n0 = blockIdx.x * 128;
    const int wm = (wid & 1) * 64;
    const int wn = (wid >> 1) * 64;

    const __half* aS[2];
    const __half* bS[2];
    aS[0] = Ah + (size_t)m0 * K;
    bS[0] = Bh + (size_t)n0 * K;
    aS[1] = (SPLIT == 3) ? (Al + (size_t)m0 * K) : aS[0];
    bS[1] = (SPLIT == 3) ? (Bl + (size_t)n0 * K) : bS[0];

    const int ldrow = tid >> 2;
    const int ldch  = tid & 3;

    const unsigned a_off = (unsigned)((lane & 15) * ROWB + (lane >> 4) * 16);
    const unsigned b_off = (unsigned)((((lane >> 4) << 3) + (lane & 7)) * ROWB
                                      + ((lane >> 3) & 1) * 16);

    float acc[4][8][4];
#pragma unroll
    for (int i = 0; i < 4; i++)
#pragma unroll
        for (int j = 0; j < 8; j++)
#pragma unroll
            for (int r = 0; r < 4; r++) acc[i][j][r] = 0.0f;

    const int NIT = K / 32;

    auto load_stage = [&](int s, int kit) {
        const int k0 = kit * 32;
        unsigned db = sb + (unsigned)(s * STAGEB);
#pragma unroll
        for (int sp = 0; sp < NSP; sp++) {
#pragma unroll
            for (int i = 0; i < 4; i++) {
                int row = ldrow + i * 32;
                CP_ASYNC16(db + (unsigned)(sp * MATB + row * ROWB + ldch * 16),
                           aS[sp] + k0 + (size_t)row * K + ldch * 8);
            }
#pragma unroll
            for (int i = 0; i < 4; i++) {
                int row = ldrow + i * 32;
                CP_ASYNC16(db + (unsigned)(BOFF + sp * MATB + row * ROWB + ldch * 16),
                           bS[sp] + k0 + (size_t)row * K + ldch * 8);
            }
        }
    };

    load_stage(0, 0);
    CP_COMMIT();

    for (int kit = 0; kit < NIT; kit++) {
        if (kit + 1 < NIT) {
            load_stage((kit + 1) & 1, kit + 1);
            CP_COMMIT();
            CP_WAIT1();
        } else {
            CP_WAIT0();
        }
        __syncthreads();

        const unsigned tb = sb + (unsigned)((kit & 1) * STAGEB);
#pragma unroll
        for (int kk = 0; kk < 32; kk += 16) {
            unsigned afr[NSP][4][4];
            unsigned bfr[NSP][4][4];
#pragma unroll
            for (int sp = 0; sp < NSP; sp++) {
#pragma unroll
                for (int mt = 0; mt < 4; mt++) {
                    unsigned ad = tb + (unsigned)(sp * MATB) + a_off
                                + (unsigned)((wm + mt * 16) * ROWB + kk * 2);
                    LDMATRIX_X4(afr[sp][mt][0], afr[sp][mt][1],
                                afr[sp][mt][2], afr[sp][mt][3], ad);
                }
#pragma unroll
                for (int nt = 0; nt < 4; nt++) {
                    unsigned bd = tb + (unsigned)(BOFF + sp * MATB) + b_off
                                + (unsigned)((wn + nt * 16) * ROWB + kk * 2);
                    LDMATRIX_X4(bfr[sp][nt][0], bfr[sp][nt][1],
                                bfr[sp][nt][2], bfr[sp][nt][3], bd);
                }
            }
#pragma unroll
            for (int mt = 0; mt < 4; mt++)
#pragma unroll
                for (int n8 = 0; n8 < 8; n8++)
                    MMAF16(acc[mt][n8], afr[0][mt][0], afr[0][mt][1],
                           afr[0][mt][2], afr[0][mt][3],
                           bfr[0][n8 >> 1][(n8 & 1) * 2],
                           bfr[0][n8 >> 1][(n8 & 1) * 2 + 1]);
            if (SPLIT == 3) {
#pragma unroll
                for (int mt = 0; mt < 4; mt++)
#pragma unroll
                    for (int n8 = 0; n8 < 8; n8++)
                        MMAF16(acc[mt][n8], afr[0][mt][0], afr[0][mt][1],
                               afr[0][mt][2], afr[0][mt][3],
                               bfr[1][n8 >> 1][(n8 & 1) * 2],
                               bfr[1][n8 >> 1][(n8 & 1) * 2 + 1]);
#pragma unroll
                for (int mt = 0; mt < 4; mt++)
#pragma unroll
                    for (int n8 = 0; n8 < 8; n8++)
                        MMAF16(acc[mt][n8], afr[1][mt][0], afr[1][mt][1],
                               afr[1][mt][2], afr[1][mt][3],
                               bfr[0][n8 >> 1][(n8 & 1) * 2],
                               bfr[0][n8 >> 1][(n8 & 1) * 2 + 1]);
            }
        }
        __syncthreads();
    }

    // ---- epilogue ----
    const int r0 = lane >> 2, c0 = (lane & 3) * 2;
#pragma unroll
    for (int mt = 0; mt < 4; mt++) {
#pragma unroll
        for (int n8 = 0; n8 < 8; n8++) {
            int row = m0 + wm + mt * 16 + r0;
            int col = n0 + wn + n8 * 8 + c0;
            float v0 = acc[mt][n8][0], v1 = acc[mt][n8][1];
            float v2 = acc[mt][n8][2], v3 = acc[mt][n8][3];
            if (OUTM == 0) {
                float* Cp = Cf + (size_t)row * N + col;
                *(float2*)Cp = make_float2(v0, v1);
                *(float2*)(Cp + (size_t)8 * N) = make_float2(v2, v3);
            } else if (OUTM == 2) {
                *(unsigned*)(Ch + (size_t)row * N + col) = pack2h(v0, v1);
                *(unsigned*)(Ch + (size_t)(row + 8) * N + col) = pack2h(v2, v3);
            } else {
                __half h0 = __float2half_rn(v0), h1 = __float2half_rn(v1);
                __half h2 = __float2half_rn(v2), h3 = __float2half_rn(v3);
                *(unsigned*)(Ch + (size_t)row * N + col) =
                    *(unsigned*)&h0 | (*(unsigned*)&h1 << 16);
                *(unsigned*)(Ch + (size_t)(row + 8) * N + col) =
                    *(unsigned*)&h2 | (*(unsigned*)&h3 << 16);
                *(unsigned*)(Cl + (size_t)row * N + col) =
                    pack2h(v0 - __half2float(h0), v1 - __half2float(h1));
                *(unsigned*)(Cl + (size_t)(row + 8) * N + col) =
                    pack2h(v2 - __half2float(h2), v3 - __half2float(h3));
            }
        }
    }
}

// ---------------------------------------------------------------------------
// HMMA flash attention (R10 version — f32-acc everywhere).
// 128q x 128k tiles, 8 warps; QK split-fp16 (3 MMAs), PV single fp16.
// bbase selects the batch range (split launch for O-projection overlap).
// ---------------------------------------------------------------------------
#define FPITCH 144
#define FMAT (128 * FPITCH)                   // 18432
#define FSTAGE (3 * FMAT)                     // Kh, Kl, V
#define FQOFF (2 * FSTAGE)                    // 110592
#define FLASH_SMEM (FQOFF + 2 * FMAT)         // 147456

__device__ __forceinline__ void load_tile_f(unsigned sdst, const __half* g, int tid) {
#pragma unroll
    for (int i = 0; i < 4; i++) {
        int c = tid + i * 256;
        int row = c >> 3, ch = c & 7;
        CP_ASYNC16(sdst + (unsigned)(row * FPITCH + ch * 16),
                   g + (size_t)row * DMODEL + ch * 8);
    }
}

__global__ __launch_bounds__(256, 1)
void flash_hmma(const __half* __restrict__ Qh, const __half* __restrict__ Ql,
                const __half* __restrict__ Kh, const __half* __restrict__ Kl,
                const __half* __restrict__ Vf, const float* __restrict__ tbl,
                __half* __restrict__ Oh, int bbase) {
    extern __shared__ char sm[];
    __shared__ float tcol[32];
    __shared__ float bias183[184];
    const unsigned sb = smem_u32(sm);
    const int tid = threadIdx.x, wid = tid >> 5, lane = tid & 31;
    const int q0 = blockIdx.x * 128, h = blockIdx.y, b = blockIdx.z + bbase;

    const size_t qbase = ((size_t)(b * S_LEN + q0)) * DMODEL + h * DKV;
    const size_t kbase = ((size_t)(b * S_LEN)) * DMODEL + h * DKV;

    load_tile_f(sb + FQOFF, Qh + qbase, tid);
    load_tile_f(sb + FQOFF + FMAT, Ql + qbase, tid);
    load_tile_f(sb, Kh + kbase, tid);
    load_tile_f(sb + FMAT, Kl + kbase, tid);
    load_tile_f(sb + 2 * FMAT, Vf + kbase, tid);
    CP_COMMIT();

    if (tid < 32) tcol[tid] = tbl[tid * NHEADS + h];
    __syncthreads();
    if (tid < 183) bias183[tid] = tcol[rel_bucket(tid - 91)];

    const int u = lane & 3, g = lane >> 2;
    const int qA = q0 + wid * 16 + g;
    const int qB = qA + 8;

    const unsigned aoff = (unsigned)((lane & 15) * FPITCH + (lane >> 4) * 16);
    const unsigned boff = (unsigned)(((((lane >> 4) << 3) | (lane & 7)) * FPITCH)
                                     + ((lane >> 3) & 1) * 16);
    const unsigned voff = (unsigned)(((((lane >> 3) & 1) * 8 + (lane & 7)) * FPITCH)
                                     + (lane >> 4) * 16);

    unsigned aqh[4][4], aql[4][4];
    float accO[8][4];
#pragma unroll
    for (int i = 0; i < 8; i++)
#pragma unroll
        for (int j = 0; j < 4; j++) accO[i][j] = 0.0f;
    float mA = -1e30f, mB = -1e30f, lA = 0.0f, lB = 0.0f;

    for (int t = 0; t < 16; t++) {
        if (t + 1 < 16) {
            unsigned st = sb + (unsigned)(((t + 1) & 1) * FSTAGE);
            size_t kb2 = kbase + (size_t)(t + 1) * 128 * DMODEL;
            load_tile_f(st, Kh + kb2, tid);
            load_tile_f(st + FMAT, Kl + kb2, tid);
            load_tile_f(st + 2 * FMAT, Vf + kb2, tid);
            CP_COMMIT();
            CP_WAIT1();
        } else {
            CP_WAIT0();
        }
        __syncthreads();

        if (t == 0) {
#pragma unroll
            for (int c = 0; c < 4; c++) {
                unsigned qa = sb + FQOFF + (unsigned)(wid * 16 * FPITCH) + aoff
                            + (unsigned)(c * 32);
                LDMATRIX_X4(aqh[c][0], aqh[c][1], aqh[c][2], aqh[c][3], qa);
                LDMATRIX_X4(aql[c][0], aql[c][1], aql[c][2], aql[c][3], qa + FMAT);
            }
        }

        const unsigned stg = sb + (unsigned)((t & 1) * FSTAGE);

        float accS[16][4];
#pragma unroll
        for (int i = 0; i < 16; i++)
#pragma unroll
            for (int j = 0; j < 4; j++) accS[i][j] = 0.0f;

#pragma unroll
        for (int c = 0; c < 4; c++) {
#pragma unroll
            for (int gp = 0; gp < 4; gp++) {
                unsigned bh[8], bl[8];
#pragma unroll
                for (int e = 0; e < 2; e++) {
                    unsigned ka = stg + boff
                                + (unsigned)((gp * 2 + e) * 16 * FPITCH + c * 32);
                    LDMATRIX_X4(bh[e * 4], bh[e * 4 + 1], bh[e * 4 + 2], bh[e * 4 + 3], ka);
                    LDMATRIX_X4(bl[e * 4], bl[e * 4 + 1], bl[e * 4 + 2], bl[e * 4 + 3],
                                ka + (unsigned)FMAT);
                }
                float* s0 = accS[4 * gp];
                float* s1 = accS[4 * gp + 1];
                float* s2 = accS[4 * gp + 2];
                float* s3 = accS[4 * gp + 3];
                MMAF16(s0, aqh[c][0], aqh[c][1], aqh[c][2], aqh[c][3], bh[0], bh[1]);
                MMAF16(s1, aqh[c][0], aqh[c][1], aqh[c][2], aqh[c][3], bh[2], bh[3]);
                MMAF16(s2, aqh[c][0], aqh[c][1], aqh[c][2], aqh[c][3], bh[4], bh[5]);
                MMAF16(s3, aqh[c][0], aqh[c][1], aqh[c][2], aqh[c][3], bh[6], bh[7]);
                MMAF16(s0, aqh[c][0], aqh[c][1], aqh[c][2], aqh[c][3], bl[0], bl[1]);
                MMAF16(s1, aqh[c][0], aqh[c][1], aqh[c][2], aqh[c][3], bl[2], bl[3]);
                MMAF16(s2, aqh[c][0], aqh[c][1], aqh[c][2], aqh[c][3], bl[4], bl[5]);
                MMAF16(s3, aqh[c][0], aqh[c][1], aqh[c][2], aqh[c][3], bl[6], bl[7]);
                MMAF16(s0, aql[c][0], aql[c][1], aql[c][2], aql[c][3], bh[0], bh[1]);
                MMAF16(s1, aql[c][0], aql[c][1], aql[c][2], aql[c][3], bh[2], bh[3]);
                MMAF16(s2, aql[c][0], aql[c][1], aql[c][2], aql[c][3], bh[4], bh[5]);
                MMAF16(s3, aql[c][0], aql[c][1], aql[c][2], aql[c][3], bh[6], bh[7]);
            }
        }

        const int k0 = t * 128;
        float tmA = -1e30f, tmB = -1e30f;
#pragma unroll
        for (int s8 = 0; s8 < 16; s8++) {
            int kc = k0 + s8 * 8 + 2 * u;
            int iA0 = min(max(kc - qA, -91), 91) + 91;
            int iA1 = min(max(kc + 1 - qA, -91), 91) + 91;
            int iB0 = min(max(kc - qB, -91), 91) + 91;
            int iB1 = min(max(kc + 1 - qB, -91), 91) + 91;
            accS[s8][0] += bias183[iA0];
            accS[s8][1] += bias183[iA1];
            accS[s8][2] += bias183[iB0];
            accS[s8][3] += bias183[iB1];
            tmA = fmaxf(tmA, fmaxf(accS[s8][0], accS[s8][1]));
            tmB = fmaxf(tmB, fmaxf(accS[s8][2], accS[s8][3]));
        }
        tmA = fmaxf(tmA, __shfl_xor_sync(0xffffffffu, tmA, 1));
        tmA = fmaxf(tmA, __shfl_xor_sync(0xffffffffu, tmA, 2));
        tmB = fmaxf(tmB, __shfl_xor_sync(0xffffffffu, tmB, 1));
        tmB = fmaxf(tmB, __shfl_xor_sync(0xffffffffu, tmB, 2));

        float nmA = fmaxf(mA, tmA), scA = __expf(mA - nmA);
        float nmB = fmaxf(mB, tmB), scB = __expf(mB - nmB);
        mA = nmA; mB = nmB;

        float sA = 0.0f, sB = 0.0f;
#pragma unroll
        for (int s8 = 0; s8 < 16; s8++) {
            accS[s8][0] = __expf(accS[s8][0] - nmA);
            accS[s8][1] = __expf(accS[s8][1] - nmA);
            accS[s8][2] = __expf(accS[s8][2] - nmB);
            accS[s8][3] = __expf(accS[s8][3] - nmB);
            sA += accS[s8][0] + accS[s8][1];
            sB += accS[s8][2] + accS[s8][3];
        }
        sA += __shfl_xor_sync(0xffffffffu, sA, 1);
        sA += __shfl_xor_sync(0xffffffffu, sA, 2);
        sB += __shfl_xor_sync(0xffffffffu, sB, 1);
        sB += __shfl_xor_sync(0xffffffffu, sB, 2);
        lA = lA * scA + sA;
        lB = lB * scB + sB;

#pragma unroll
        for (int nt = 0; nt < 8; nt++) {
            accO[nt][0] *= scA; accO[nt][1] *= scA;
            accO[nt][2] *= scB; accO[nt][3] *= scB;
        }

#pragma unroll
        for (int j = 0; j < 8; j++) {
            unsigned a0 = pack2h(accS[2 * j][0], accS[2 * j][1]);
            unsigned a1 = pack2h(accS[2 * j][2], accS[2 * j][3]);
            unsigned a2 = pack2h(accS[2 * j + 1][0], accS[2 * j + 1][1]);
            unsigned a3 = pack2h(accS[2 * j + 1][2], accS[2 * j + 1][3]);
#pragma unroll
            for (int g2 = 0; g2 < 4; g2++) {
                unsigned bv0, bv1, bv2, bv3;
                unsigned va = stg + (unsigned)(2 * FMAT) + voff
                            + (unsigned)(j * 16 * FPITCH + g2 * 32);
                LDMATRIX_X4_T(bv0, bv1, bv2, bv3, va);
                MMAF16(accO[2 * g2], a0, a1, a2, a3, bv0, bv1);
                MMAF16(accO[2 * g2 + 1], a0, a1, a2, a3, bv2, bv3);
            }
        }
        __syncthreads();
    }

    const float iA = 1.0f / lA, iB = 1.0f / lB;
    const size_t rowA = (size_t)(b * S_LEN + qA) * DMODEL + h * DKV;
    const size_t rowB = (size_t)(b * S_LEN + qB) * DMODEL + h * DKV;
#pragma unroll
    for (int nt = 0; nt < 8; nt++) {
        int col = nt * 8 + 2 * u;
        *(unsigned*)(Oh + rowA + col) = pack2h(accO[nt][0] * iA, accO[nt][1] * iA);
        *(unsigned*)(Oh + rowB + col) = pack2h(accO[nt][2] * iB, accO[nt][3] * iB);
    }
}

// ---------------------------------------------------------------------------
extern "C" void kernel_launch(void* const* d_in, const int* in_sizes, int n_in,
                              void* d_out, int out_size) {
    const float* X   = (const float*)d_in[0];
    const float* Wq  = (const float*)d_in[1];
    const float* Wk  = (const float*)d_in[2];
    const float* Wv  = (const float*)d_in[3];
    const float* Wo  = (const float*)d_in[4];
    const float* tbl = (const float*)d_in[5];
    float* out = (float*)d_out;

    __half *xh, *xl, *wqh, *wql, *wkh, *wkl, *wvh, *wvl, *woh, *wol;
    __half *qh, *ql, *kh, *kl, *vh, *oh;
    cudaGetSymbolAddress((void**)&xh, g_xh);
    cudaGetSymbolAddress((void**)&xl, g_xl);
    cudaGetSymbolAddress((void**)&wqh, g_wqh);
    cudaGetSymbolAddress((void**)&wql, g_wql);
    cudaGetSymbolAddress((void**)&wkh, g_wkh);
    cudaGetSymbolAddress((void**)&wkl, g_wkl);
    cudaGetSymbolAddress((void**)&wvh, g_wvh);
    cudaGetSymbolAddress((void**)&wvl, g_wvl);
    cudaGetSymbolAddress((void**)&woh, g_woh);
    cudaGetSymbolAddress((void**)&wol, g_wol);
    cudaGetSymbolAddress((void**)&qh, g_qh);
    cudaGetSymbolAddress((void**)&ql, g_ql);
    cudaGetSymbolAddress((void**)&kh, g_kh);
    cudaGetSymbolAddress((void**)&kl, g_kl);
    cudaGetSymbolAddress((void**)&vh, g_vh);
    cudaGetSymbolAddress((void**)&oh, g_oh);

    static cudaStream_t s2 = nullptr, s3 = nullptr, s4 = nullptr;
    static cudaEvent_t evFork = nullptr, evJoin = nullptr;
    static cudaEvent_t evConv = nullptr, evK = nullptr, evV = nullptr;
    static cudaEvent_t evQ = nullptr, evO2 = nullptr;
    if (s2 == nullptr) {
        cudaStreamCreateWithFlags(&s2, cudaStreamNonBlocking);
        cudaStreamCreateWithFlags(&s3, cudaStreamNonBlocking);
        cudaStreamCreateWithFlags(&s4, cudaStreamNonBlocking);
        cudaEventCreateWithFlags(&evFork, cudaEventDisableTiming);
        cudaEventCreateWithFlags(&evJoin, cudaEventDisableTiming);
        cudaEventCreateWithFlags(&evConv, cudaEventDisableTiming);
        cudaEventCreateWithFlags(&evK, cudaEventDisableTiming);
        cudaEventCreateWithFlags(&evV, cudaEventDisableTiming);
        cudaEventCreateWithFlags(&evQ, cudaEventDisableTiming);
        cudaEventCreateWithFlags(&evO2, cudaEventDisableTiming);
    }

    // ---- fork: pos_bias on side stream ----
    cudaEventRecord(evFork, 0);
    cudaStreamWaitEvent(s2, evFork, 0);
    {
        dim3 bg(S_LEN, NHEADS);
        bias_kernel<<<bg, 256, 0, s2>>>(tbl, out + OUT_ELEMS);
    }
    cudaEventRecord(evJoin, s2);

    // ---- conversions (main stream) ----
    conv_all<<<12288, 256>>>(X, xh, xl, Wq, wqh, wql, Wk, wkh, wkl,
                             Wv, wvh, wvl, Wo, woh, wol);
    cudaEventRecord(evConv, 0);
    cudaStreamWaitEvent(s3, evConv, 0);
    cudaStreamWaitEvent(s4, evConv, 0);

    dim3 gg(DMODEL / 128, M_ROWS / 128);      // (8, 64) = 512 CTAs

    cudaFuncSetAttribute(gemm_h<3, 1>, cudaFuncAttributeMaxDynamicSharedMemorySize,
                         2 * 4 * MATB);
    cudaFuncSetAttribute(gemm_h<1, 2>, cudaFuncAttributeMaxDynamicSharedMemorySize,
                         2 * 2 * MATB);
    cudaFuncSetAttribute(gemm_h<1, 0>, cudaFuncAttributeMaxDynamicSharedMemorySize,
                         2 * 2 * MATB);
    cudaFuncSetAttribute(flash_hmma, cudaFuncAttributeMaxDynamicSharedMemorySize,
                         FLASH_SMEM);

    // Q on main, K on s3, V on s4 — independent, tails overlap
    gemm_h<3, 1><<<gg, 128, 2 * 4 * MATB>>>(xh, xl, wqh, wql,
                                            nullptr, qh, ql,
                                            M_ROWS, DMODEL, DMODEL);
    cudaEventRecord(evQ, 0);
    gemm_h<3, 1><<<gg, 128, 2 * 4 * MATB, s3>>>(xh, xl, wkh, wkl,
                                                nullptr, kh, kl,
                                                M_ROWS, DMODEL, DMODEL);
    cudaEventRecord(evK, s3);
    gemm_h<1, 2><<<gg, 128, 2 * 2 * MATB, s4>>>(xh, nullptr, wvh, nullptr,
                                                nullptr, vh, nullptr,
                                                M_ROWS, DMODEL, DMODEL);
    cudaEventRecord(evV, s4);

    // flash half 1 (b=0,1) on main; flash half 2 (b=2,3) on s3
    cudaStreamWaitEvent(0, evK, 0);
    cudaStreamWaitEvent(0, evV, 0);
    cudaStreamWaitEvent(s3, evQ, 0);
    cudaStreamWaitEvent(s3, evV, 0);

    dim3 fgh(S_LEN / 128, NHEADS, BATCH / 2);
    flash_hmma<<<fgh, 256, FLASH_SMEM>>>(qh, ql, kh, kl, vh, tbl, oh, 0);
    flash_hmma<<<fgh, 256, FLASH_SMEM, s3>>>(qh, ql, kh, kl, vh, tbl, oh, 2);

    // O-projection split by M halves: O1 (rows of b=0,1) overlaps flash half 2
    dim3 ggh(DMODEL / 128, M_ROWS / 2 / 128);   // (8, 32) = 256 CTAs
    const int MH = M_ROWS / 2;
    gemm_h<1, 0><<<ggh, 128, 2 * 2 * MATB>>>(oh, nullptr, woh, nullptr,
                                             out, nullptr, nullptr,
                                             MH, DMODEL, DMODEL);
    gemm_h<1, 0><<<ggh, 128, 2 * 2 * MATB, s3>>>(oh + (size_t)MH * DMODEL, nullptr,
                                                 woh, nullptr,
                                                 out + (size_t)MH * DMODEL,
                                                 nullptr, nullptr,
                                                 MH, DMODEL, DMODEL);
    cudaEventRecord(evO2, s3);
    cudaStreamWaitEvent(0, evO2, 0);

    // ---- join: pos_bias must complete before kernel_launch's work is done ----
    cudaStreamWaitEvent(0, evJoin, 0);
}

// round 16
// speedup vs baseline: 1.5783x; 1.0235x over previous
#include <cuda_runtime.h>
#include <cuda_fp16.h>
#include <math.h>

// Problem constants (fixed shapes)
#define S_LEN   2048
#define BATCH   4
#define NHEADS  16
#define DKV     64
#define DMODEL  1024
#define M_ROWS  (BATCH * S_LEN)                 // 8192
#define OUT_ELEMS  (M_ROWS * DMODEL)            // 8388608
#define BIAS_ELEMS (NHEADS * S_LEN * S_LEN)     // 67108864

// ---------------------------------------------------------------------------
// Device scratch (fp16 everywhere)
// ---------------------------------------------------------------------------
__device__ __half g_xh[M_ROWS * DMODEL];
__device__ __half g_xl[M_ROWS * DMODEL];
__device__ __half g_wqh[DMODEL * DMODEL];
__device__ __half g_wql[DMODEL * DMODEL];
__device__ __half g_wkh[DMODEL * DMODEL];
__device__ __half g_wkl[DMODEL * DMODEL];
__device__ __half g_wvh[DMODEL * DMODEL];
__device__ __half g_wvl[DMODEL * DMODEL];
__device__ __half g_woh[DMODEL * DMODEL];
__device__ __half g_wol[DMODEL * DMODEL];
__device__ __half g_qh[M_ROWS * DMODEL];
__device__ __half g_ql[M_ROWS * DMODEL];
__device__ __half g_kh[M_ROWS * DMODEL];
__device__ __half g_kl[M_ROWS * DMODEL];
__device__ __half g_vh[M_ROWS * DMODEL];
__device__ __half g_oh[M_ROWS * DMODEL];

// ---------------------------------------------------------------------------
// PTX helpers (sm_80-level only)
// ---------------------------------------------------------------------------
__device__ __forceinline__ unsigned smem_u32(const void* p) {
    unsigned a;
    asm("{ .reg .u64 t; cvta.to.shared.u64 t, %1; cvt.u32.u64 %0, t; }"
        : "=r"(a) : "l"(p));
    return a;
}

#define LDMATRIX_X4(r0, r1, r2, r3, addr)                                      \
    asm volatile("ldmatrix.sync.aligned.m8n8.x4.shared.b16 {%0,%1,%2,%3}, [%4];" \
                 : "=r"(r0), "=r"(r1), "=r"(r2), "=r"(r3) : "r"(addr))

#define LDMATRIX_X4_T(r0, r1, r2, r3, addr)                                    \
    asm volatile("ldmatrix.sync.aligned.m8n8.x4.trans.shared.b16 {%0,%1,%2,%3}, [%4];" \
                 : "=r"(r0), "=r"(r1), "=r"(r2), "=r"(r3) : "r"(addr))

#define MMAF16(d, a0, a1, a2, a3, b0, b1)                                      \
    asm volatile("mma.sync.aligned.m16n8k16.row.col.f32.f16.f16.f32 "          \
                 "{%0,%1,%2,%3},{%4,%5,%6,%7},{%8,%9},{%0,%1,%2,%3};"          \
                 : "+f"((d)[0]), "+f"((d)[1]), "+f"((d)[2]), "+f"((d)[3])      \
                 : "r"(a0), "r"(a1), "r"(a2), "r"(a3), "r"(b0), "r"(b1))

#define CP_ASYNC16(dst, src)                                                   \
    asm volatile("cp.async.cg.shared.global [%0], [%1], 16;"                   \
                 :: "r"(dst), "l"(src) : "memory")
#define CP_COMMIT() asm volatile("cp.async.commit_group;" ::: "memory")
#define CP_WAIT1()  asm volatile("cp.async.wait_group 1;" ::: "memory")
#define CP_WAIT0()  asm volatile("cp.async.wait_group 0;" ::: "memory")

__device__ __forceinline__ unsigned pack2h(float a, float b) {
    __half2 h = __floats2half2_rn(a, b);
    return *reinterpret_cast<unsigned*>(&h);
}

// ---------------------------------------------------------------------------
// Relative-position bucket (exact integer reformulation of the reference)
// ---------------------------------------------------------------------------
__device__ __forceinline__ int rel_bucket(int rel) {
    int ret = (rel > 0) ? 16 : 0;
    int rp  = (rel < 0) ? -rel : rel;
    int off;
    if (rp < 8) {
        off = rp;
    } else {
        off = 8 + (rp >= 12) + (rp >= 16) + (rp >= 23) + (rp >= 32)
                + (rp >= 46) + (rp >= 64) + (rp >= 91);
    }
    return ret + off;
}

// ---------------------------------------------------------------------------
// pos_bias writer (float4 stores) — runs on forked stream
// ---------------------------------------------------------------------------
__global__ __launch_bounds__(256) void bias_kernel(const float* __restrict__ tbl,
                                                   float* __restrict__ outb) {
    __shared__ float tcol[32];
    const int q = blockIdx.x;
    const int h = blockIdx.y;
    if (threadIdx.x < 32) tcol[threadIdx.x] = tbl[threadIdx.x * NHEADS + h];
    __syncthreads();
    float4* row = (float4*)(outb + ((size_t)h * S_LEN + q) * S_LEN);
#pragma unroll
    for (int it = 0; it < 2; it++) {
        int k4 = threadIdx.x + it * 256;
        int k = k4 * 4;
        float4 v = make_float4(tcol[rel_bucket(k - q)],
                               tcol[rel_bucket(k + 1 - q)],
                               tcol[rel_bucket(k + 2 - q)],
                               tcol[rel_bucket(k + 3 - q)]);
        row[k4] = v;
    }
}

// ---------------------------------------------------------------------------
// ALL conversions in one launch
// ---------------------------------------------------------------------------
__global__ __launch_bounds__(256) void conv_all(
    const float* __restrict__ X,  __half* __restrict__ xh,  __half* __restrict__ xl,
    const float* __restrict__ Wq, __half* __restrict__ wqh, __half* __restrict__ wql,
    const float* __restrict__ Wk, __half* __restrict__ wkh, __half* __restrict__ wkl,
    const float* __restrict__ Wv, __half* __restrict__ wvh, __half* __restrict__ wvl,
    const float* __restrict__ Wo, __half* __restrict__ woh, __half* __restrict__ wol) {
    const int tid = threadIdx.x;
    if (blockIdx.x < 8192) {
        int idx = blockIdx.x * 256 + tid;
        float4 v = ((const float4*)X)[idx];
        __half h0 = __float2half_rn(v.x), h1 = __float2half_rn(v.y);
        __half h2 = __float2half_rn(v.z), h3 = __float2half_rn(v.w);
        unsigned* H = (unsigned*)xh;
        unsigned* L = (unsigned*)xl;
        H[idx * 2]     = pack2h(v.x, v.y);
        H[idx * 2 + 1] = pack2h(v.z, v.w);
        L[idx * 2]     = pack2h(v.x - __half2float(h0), v.y - __half2float(h1));
        L[idx * 2 + 1] = pack2h(v.z - __half2float(h2), v.w - __half2float(h3));
        return;
    }
    __shared__ float t[32][33];
    const int wi = blockIdx.x - 8192;
    const float* W;
    __half *Th, *Tl;
    switch (wi >> 10) {
        case 0:  W = Wq; Th = wqh; Tl = wql; break;
        case 1:  W = Wk; Th = wkh; Tl = wkl; break;
        case 2:  W = Wv; Th = wvh; Tl = wvl; break;
        default: W = Wo; Th = woh; Tl = wol; break;
    }
    const int b  = wi & 1023;
    const int nb = (b & 31) * 32, kb = (b >> 5) * 32;
    const int tx = tid & 31, ty = tid >> 5;
#pragma unroll
    for (int r = ty; r < 32; r += 8)
        t[r][tx] = W[(size_t)(kb + r) * DMODEL + nb + tx];
    __syncthreads();
#pragma unroll
    for (int r = ty; r < 32; r += 8) {
        float v = t[tx][r];  // = W[kb+tx][nb+r]
        __half h = __float2half_rn(v);
        Th[(size_t)(nb + r) * DMODEL + kb + tx] = h;
        Tl[(size_t)(nb + r) * DMODEL + kb + tx] =
            __float2half_rn(v - __half2float(h));
    }
}

// ---------------------------------------------------------------------------
// HMMA fp16 GEMM (R8/R10 config — best measured):
//   SPLIT==3: C = AhBh + AhBl + AlBh   SPLIT==1: C = AhBh  (all f32-acc)
//   OUTM: 0 -> float C; 1 -> fp16 hi/lo pair; 2 -> fp16 single
// CTA tile 128x128, BK=32, 4 warps @ 64x64, 2-stage cp.async, 2 CTAs/SM.
// ---------------------------------------------------------------------------
#define ROWB 80                               // 32 fp16 (64B) + 16B pad
#define MATB (128 * ROWB)                     // 10240 B (128 rows)

template<int SPLIT, int OUTM>
__global__ __launch_bounds__(128, 2)
void gemm_h(const __half* __restrict__ Ah, const __half* __restrict__ Al,
            const __half* __restrict__ Bh, const __half* __restrict__ Bl,
            float* __restrict__ Cf, __half* __restrict__ Ch,
            __half* __restrict__ Cl, int M, int N, int K) {
    constexpr int NSP = (SPLIT == 3) ? 2 : 1;
    constexpr int STAGEB = NSP * 2 * MATB;
    constexpr int BOFF = NSP * MATB;
    extern __shared__ char smx[];
    const unsigned sb = smem_u32(smx);
    const int tid  = threadIdx.x;
    const int wid  = tid >> 5;
    const int lane = tid & 31;
    const int m0 = blockIdx.y * 128, n0 = blockIdx.x * 128;
    const int wm = (wid & 1) * 64;
    const int wn = (wid >> 1) * 64;

    const __half* aS[2];
    const __half* bS[2];
    aS[0] = Ah + (size_t)m0 * K;
    bS[0] = Bh + (size_t)n0 * K;
    aS[1] = (SPLIT == 3) ? (Al + (size_t)m0 * K) : aS[0];
    bS[1] = (SPLIT == 3) ? (Bl + (size_t)n0 * K) : bS[0];

    const int ldrow = tid >> 2;
    const int ldch  = tid & 3;

    const unsigned a_off = (unsigned)((lane & 15) * ROWB + (lane >> 4) * 16);
    const unsigned b_off = (unsigned)((((lane >> 4) << 3) + (lane & 7)) * ROWB
                                      + ((lane >> 3) & 1) * 16);

    float acc[4][8][4];
#pragma unroll
    for (int i = 0; i < 4; i++)
#pragma unroll
        for (int j = 0; j < 8; j++)
#pragma unroll
            for (int r = 0; r < 4; r++) acc[i][j][r] = 0.0f;

    const int NIT = K / 32;

    auto load_stage = [&](int s, int kit) {
        const int k0 = kit * 32;
        unsigned db = sb + (unsigned)(s * STAGEB);
#pragma unroll
        for (int sp = 0; sp < NSP; sp++) {
#pragma unroll
            for (int i = 0; i < 4; i++) {
                int row = ldrow + i * 32;
                CP_ASYNC16(db + (unsigned)(sp * MATB + row * ROWB + ldch * 16),
                           aS[sp] + k0 + (size_t)row * K + ldch * 8);
            }
#pragma unroll
            for (int i = 0; i < 4; i++) {
                int row = ldrow + i * 32;
                CP_ASYNC16(db + (unsigned)(BOFF + sp * MATB + row * ROWB + ldch * 16),
                           bS[sp] + k0 + (size_t)row * K + ldch * 8);
            }
        }
    };

    load_stage(0, 0);
    CP_COMMIT();

    for (int kit = 0; kit < NIT; kit++) {
        if (kit + 1 < NIT) {
            load_stage((kit + 1) & 1, kit + 1);
            CP_COMMIT();
            CP_WAIT1();
        } else {
            CP_WAIT0();
        }
        __syncthreads();

        const unsigned tb = sb + (unsigned)((kit & 1) * STAGEB);
#pragma unroll
        for (int kk = 0; kk < 32; kk += 16) {
            unsigned afr[NSP][4][4];
            unsigned bfr[NSP][4][4];
#pragma unroll
            for (int sp = 0; sp < NSP; sp++) {
#pragma unroll
                for (int mt = 0; mt < 4; mt++) {
                    unsigned ad = tb + (unsigned)(sp * MATB) + a_off
                                + (unsigned)((wm + mt * 16) * ROWB + kk * 2);
                    LDMATRIX_X4(afr[sp][mt][0], afr[sp][mt][1],
                                afr[sp][mt][2], afr[sp][mt][3], ad);
                }
#pragma unroll
                for (int nt = 0; nt < 4; nt++) {
                    unsigned bd = tb + (unsigned)(BOFF + sp * MATB) + b_off
                                + (unsigned)((wn + nt * 16) * ROWB + kk * 2);
                    LDMATRIX_X4(bfr[sp][nt][0], bfr[sp][nt][1],
                                bfr[sp][nt][2], bfr[sp][nt][3], bd);
                }
            }
#pragma unroll
            for (int mt = 0; mt < 4; mt++)
#pragma unroll
                for (int n8 = 0; n8 < 8; n8++)
                    MMAF16(acc[mt][n8], afr[0][mt][0], afr[0][mt][1],
                           afr[0][mt][2], afr[0][mt][3],
                           bfr[0][n8 >> 1][(n8 & 1) * 2],
                           bfr[0][n8 >> 1][(n8 & 1) * 2 + 1]);
            if (SPLIT == 3) {
#pragma unroll
                for (int mt = 0; mt < 4; mt++)
#pragma unroll
                    for (int n8 = 0; n8 < 8; n8++)
                        MMAF16(acc[mt][n8], afr[0][mt][0], afr[0][mt][1],
                               afr[0][mt][2], afr[0][mt][3],
                               bfr[1][n8 >> 1][(n8 & 1) * 2],
                               bfr[1][n8 >> 1][(n8 & 1) * 2 + 1]);
#pragma unroll
                for (int mt = 0; mt < 4; mt++)
#pragma unroll
                    for (int n8 = 0; n8 < 8; n8++)
                        MMAF16(acc[mt][n8], afr[1][mt][0], afr[1][mt][1],
                               afr[1][mt][2], afr[1][mt][3],
                               bfr[0][n8 >> 1][(n8 & 1) * 2],
                               bfr[0][n8 >> 1][(n8 & 1) * 2 + 1]);
            }
        }
        __syncthreads();
    }

    // ---- epilogue ----
    const int r0 = lane >> 2, c0 = (lane & 3) * 2;
#pragma unroll
    for (int mt = 0; mt < 4; mt++) {
#pragma unroll
        for (int n8 = 0; n8 < 8; n8++) {
            int row = m0 + wm + mt * 16 + r0;
            int col = n0 + wn + n8 * 8 + c0;
            float v0 = acc[mt][n8][0], v1 = acc[mt][n8][1];
            float v2 = acc[mt][n8][2], v3 = acc[mt][n8][3];
            if (OUTM == 0) {
                float* Cp = Cf + (size_t)row * N + col;
                *(float2*)Cp = make_float2(v0, v1);
                *(float2*)(Cp + (size_t)8 * N) = make_float2(v2, v3);
            } else if (OUTM == 2) {
                *(unsigned*)(Ch + (size_t)row * N + col) = pack2h(v0, v1);
                *(unsigned*)(Ch + (size_t)(row + 8) * N + col) = pack2h(v2, v3);
            } else {
                __half h0 = __float2half_rn(v0), h1 = __float2half_rn(v1);
                __half h2 = __float2half_rn(v2), h3 = __float2half_rn(v3);
                *(unsigned*)(Ch + (size_t)row * N + col) =
                    *(unsigned*)&h0 | (*(unsigned*)&h1 << 16);
                *(unsigned*)(Ch + (size_t)(row + 8) * N + col) =
                    *(unsigned*)&h2 | (*(unsigned*)&h3 << 16);
                *(unsigned*)(Cl + (size_t)row * N + col) =
                    pack2h(v0 - __half2float(h0), v1 - __half2float(h1));
                *(unsigned*)(Cl + (size_t)(row + 8) * N + col) =
                    pack2h(v2 - __half2float(h2), v3 - __half2float(h3));
            }
        }
    }
}

// ---------------------------------------------------------------------------
// HMMA flash attention, 128q x 64k tiles, 2 CTAs/SM (92 KB smem, <=128 regs).
// QK split-fp16 (3 MMA passes, f32-acc), PV single fp16 (f32-acc).
// Q fragments reloaded per-c (transient) to stay under the register bound.
// Same online-softmax recurrence as the 128k version (same math, finer tiles).
// ---------------------------------------------------------------------------
#define FPITCH 144
#define FTILE (64 * FPITCH)                   // 9216  (64-row K/V tile)
#define FSTAGE (3 * FTILE)                    // 27648 (Kh, Kl, V)
#define FQOFF (2 * FSTAGE)                    // 55296
#define FQMAT (128 * FPITCH)                  // 18432 (128-row Q tile)
#define FLASH_SMEM (FQOFF + 2 * FQMAT)        // 92160

__device__ __forceinline__ void load_tile64(unsigned sdst, const __half* g, int tid) {
#pragma unroll
    for (int i = 0; i < 2; i++) {
        int c = tid + i * 256;
        int row = c >> 3, ch = c & 7;
        CP_ASYNC16(sdst + (unsigned)(row * FPITCH + ch * 16),
                   g + (size_t)row * DMODEL + ch * 8);
    }
}

__device__ __forceinline__ void load_tile128(unsigned sdst, const __half* g, int tid) {
#pragma unroll
    for (int i = 0; i < 4; i++) {
        int c = tid + i * 256;
        int row = c >> 3, ch = c & 7;
        CP_ASYNC16(sdst + (unsigned)(row * FPITCH + ch * 16),
                   g + (size_t)row * DMODEL + ch * 8);
    }
}

__global__ __launch_bounds__(256, 2)
void flash_hmma(const __half* __restrict__ Qh, const __half* __restrict__ Ql,
                const __half* __restrict__ Kh, const __half* __restrict__ Kl,
                const __half* __restrict__ Vf, const float* __restrict__ tbl,
                __half* __restrict__ Oh, int bbase) {
    extern __shared__ char sm[];
    __shared__ float tcol[32];
    __shared__ float bias183[184];
    const unsigned sb = smem_u32(sm);
    const int tid = threadIdx.x, wid = tid >> 5, lane = tid & 31;
    const int q0 = blockIdx.x * 128, h = blockIdx.y, b = blockIdx.z + bbase;

    const size_t qbase = ((size_t)(b * S_LEN + q0)) * DMODEL + h * DKV;
    const size_t kbase = ((size_t)(b * S_LEN)) * DMODEL + h * DKV;

    // group 0: Q (hi+lo, 128 rows) + K/V tile 0 (64 rows each)
    load_tile128(sb + FQOFF, Qh + qbase, tid);
    load_tile128(sb + FQOFF + FQMAT, Ql + qbase, tid);
    load_tile64(sb, Kh + kbase, tid);
    load_tile64(sb + FTILE, Kl + kbase, tid);
    load_tile64(sb + 2 * FTILE, Vf + kbase, tid);
    CP_COMMIT();

    if (tid < 32) tcol[tid] = tbl[tid * NHEADS + h];
    __syncthreads();
    if (tid < 183) bias183[tid] = tcol[rel_bucket(tid - 91)];

    const int u = lane & 3, g = lane >> 2;
    const int qA = q0 + wid * 16 + g;
    const int qB = qA + 8;

    const unsigned aoff = (unsigned)((lane & 15) * FPITCH + (lane >> 4) * 16);
    const unsigned boff = (unsigned)(((((lane >> 4) << 3) | (lane & 7)) * FPITCH)
                                     + ((lane >> 3) & 1) * 16);
    const unsigned voff = (unsigned)(((((lane >> 3) & 1) * 8 + (lane & 7)) * FPITCH)
                                     + (lane >> 4) * 16);

    float accO[8][4];
#pragma unroll
    for (int i = 0; i < 8; i++)
#pragma unroll
        for (int j = 0; j < 4; j++) accO[i][j] = 0.0f;
    float mA = -1e30f, mB = -1e30f, lA = 0.0f, lB = 0.0f;

    for (int t = 0; t < 32; t++) {
        if (t + 1 < 32) {
            unsigned st = sb + (unsigned)(((t + 1) & 1) * FSTAGE);
            size_t kb2 = kbase + (size_t)(t + 1) * 64 * DMODEL;
            load_tile64(st, Kh + kb2, tid);
            load_tile64(st + FTILE, Kl + kb2, tid);
            load_tile64(st + 2 * FTILE, Vf + kb2, tid);
            CP_COMMIT();
            CP_WAIT1();
        } else {
            CP_WAIT0();
        }
        __syncthreads();

        const unsigned stg = sb + (unsigned)((t & 1) * FSTAGE);

        // ---- S = Q K^T (split fp16, f32 accum); Q frags transient per-c ----
        float accS[8][4];
#pragma unroll
        for (int i = 0; i < 8; i++)
#pragma unroll
            for (int j = 0; j < 4; j++) accS[i][j] = 0.0f;

#pragma unroll
        for (int c = 0; c < 4; c++) {
            unsigned aq0, aq1, aq2, aq3, al0, al1, al2, al3;
            unsigned qa = sb + FQOFF + (unsigned)(wid * 16 * FPITCH) + aoff
                        + (unsigned)(c * 32);
            LDMATRIX_X4(aq0, aq1, aq2, aq3, qa);
            LDMATRIX_X4(al0, al1, al2, al3, qa + (unsigned)FQMAT);
#pragma unroll
            for (int gp = 0; gp < 2; gp++) {
                unsigned bh[8], bl[8];
#pragma unroll
                for (int e = 0; e < 2; e++) {
                    unsigned ka = stg + boff
                                + (unsigned)((gp * 2 + e) * 16 * FPITCH + c * 32);
                    LDMATRIX_X4(bh[e * 4], bh[e * 4 + 1], bh[e * 4 + 2], bh[e * 4 + 3], ka);
                    LDMATRIX_X4(bl[e * 4], bl[e * 4 + 1], bl[e * 4 + 2], bl[e * 4 + 3],
                                ka + (unsigned)FTILE);
                }
                float* s0 = accS[4 * gp];
                float* s1 = accS[4 * gp + 1];
                float* s2 = accS[4 * gp + 2];
                float* s3 = accS[4 * gp + 3];
                // pass 1: qh * kh
                MMAF16(s0, aq0, aq1, aq2, aq3, bh[0], bh[1]);
                MMAF16(s1, aq0, aq1, aq2, aq3, bh[2], bh[3]);
                MMAF16(s2, aq0, aq1, aq2, aq3, bh[4], bh[5]);
                MMAF16(s3, aq0, aq1, aq2, aq3, bh[6], bh[7]);
                // pass 2: qh * kl
                MMAF16(s0, aq0, aq1, aq2, aq3, bl[0], bl[1]);
                MMAF16(s1, aq0, aq1, aq2, aq3, bl[2], bl[3]);
                MMAF16(s2, aq0, aq1, aq2, aq3, bl[4], bl[5]);
                MMAF16(s3, aq0, aq1, aq2, aq3, bl[6], bl[7]);
                // pass 3: ql * kh
                MMAF16(s0, al0, al1, al2, al3, bh[0], bh[1]);
                MMAF16(s1, al0, al1, al2, al3, bh[2], bh[3]);
                MMAF16(s2, al0, al1, al2, al3, bh[4], bh[5]);
                MMAF16(s3, al0, al1, al2, al3, bh[6], bh[7]);
            }
        }

        // ---- bias + online softmax (64-k tile) ----
        const int k0 = t * 64;
        float tmA = -1e30f, tmB = -1e30f;
#pragma unroll
        for (int s8 = 0; s8 < 8; s8++) {
            int kc = k0 + s8 * 8 + 2 * u;
            int iA0 = min(max(kc - qA, -91), 91) + 91;
            int iA1 = min(max(kc + 1 - qA, -91), 91) + 91;
            int iB0 = min(max(kc - qB, -91), 91) + 91;
            int iB1 = min(max(kc + 1 - qB, -91), 91) + 91;
            accS[s8][0] += bias183[iA0];
            accS[s8][1] += bias183[iA1];
            accS[s8][2] += bias183[iB0];
            accS[s8][3] += bias183[iB1];
            tmA = fmaxf(tmA, fmaxf(accS[s8][0], accS[s8][1]));
            tmB = fmaxf(tmB, fmaxf(accS[s8][2], accS[s8][3]));
        }
        tmA = fmaxf(tmA, __shfl_xor_sync(0xffffffffu, tmA, 1));
        tmA = fmaxf(tmA, __shfl_xor_sync(0xffffffffu, tmA, 2));
        tmB = fmaxf(tmB, __shfl_xor_sync(0xffffffffu, tmB, 1));
        tmB = fmaxf(tmB, __shfl_xor_sync(0xffffffffu, tmB, 2));

        float nmA = fmaxf(mA, tmA), scA = __expf(mA - nmA);
        float nmB = fmaxf(mB, tmB), scB = __expf(mB - nmB);
        mA = nmA; mB = nmB;

        float sA = 0.0f, sB = 0.0f;
#pragma unroll
        for (int s8 = 0; s8 < 8; s8++) {
            accS[s8][0] = __expf(accS[s8][0] - nmA);
            accS[s8][1] = __expf(accS[s8][1] - nmA);
            accS[s8][2] = __expf(accS[s8][2] - nmB);
            accS[s8][3] = __expf(accS[s8][3] - nmB);
            sA += accS[s8][0] + accS[s8][1];
            sB += accS[s8][2] + accS[s8][3];
        }
        sA += __shfl_xor_sync(0xffffffffu, sA, 1);
        sA += __shfl_xor_sync(0xffffffffu, sA, 2);
        sB += __shfl_xor_sync(0xffffffffu, sB, 1);
        sB += __shfl_xor_sync(0xffffffffu, sB, 2);
        lA = lA * scA + sA;
        lB = lB * scB + sB;

#pragma unroll
        for (int nt = 0; nt < 8; nt++) {
            accO[nt][0] *= scA; accO[nt][1] *= scA;
            accO[nt][2] *= scB; accO[nt][3] *= scB;
        }

        // ---- O += P V (fragment chaining, fp16 P & V, f32 acc) ----
#pragma unroll
        for (int j = 0; j < 4; j++) {
            unsigned a0 = pack2h(accS[2 * j][0], accS[2 * j][1]);
            unsigned a1 = pack2h(accS[2 * j][2], accS[2 * j][3]);
            unsigned a2 = pack2h(accS[2 * j + 1][0], accS[2 * j + 1][1]);
            unsigned a3 = pack2h(accS[2 * j + 1][2], accS[2 * j + 1][3]);
#pragma unroll
            for (int g2 = 0; g2 < 4; g2++) {
                unsigned bv0, bv1, bv2, bv3;
                unsigned va = stg + (unsigned)(2 * FTILE) + voff
                            + (unsigned)(j * 16 * FPITCH + g2 * 32);
                LDMATRIX_X4_T(bv0, bv1, bv2, bv3, va);
                MMAF16(accO[2 * g2], a0, a1, a2, a3, bv0, bv1);
                MMAF16(accO[2 * g2 + 1], a0, a1, a2, a3, bv2, bv3);
            }
        }
        __syncthreads();
    }

    // ---- epilogue: normalize, write fp16 ----
    const float iA = 1.0f / lA, iB = 1.0f / lB;
    const size_t rowA = (size_t)(b * S_LEN + qA) * DMODEL + h * DKV;
    const size_t rowB = (size_t)(b * S_LEN + qB) * DMODEL + h * DKV;
#pragma unroll
    for (int nt = 0; nt < 8; nt++) {
        int col = nt * 8 + 2 * u;
        *(unsigned*)(Oh + rowA + col) = pack2h(accO[nt][0] * iA, accO[nt][1] * iA);
        *(unsigned*)(Oh + rowB + col) = pack2h(accO[nt][2] * iB, accO[nt][3] * iB);
    }
}

// ---------------------------------------------------------------------------
extern "C" void kernel_launch(void* const* d_in, const int* in_sizes, int n_in,
                              void* d_out, int out_size) {
    const float* X   = (const float*)d_in[0];
    const float* Wq  = (const float*)d_in[1];
    const float* Wk  = (const float*)d_in[2];
    const float* Wv  = (const float*)d_in[3];
    const float* Wo  = (const float*)d_in[4];
    const float* tbl = (const float*)d_in[5];
    float* out = (float*)d_out;

    __half *xh, *xl, *wqh, *wql, *wkh, *wkl, *wvh, *wvl, *woh, *wol;
    __half *qh, *ql, *kh, *kl, *vh, *oh;
    cudaGetSymbolAddress((void**)&xh, g_xh);
    cudaGetSymbolAddress((void**)&xl, g_xl);
    cudaGetSymbolAddress((void**)&wqh, g_wqh);
    cudaGetSymbolAddress((void**)&wql, g_wql);
    cudaGetSymbolAddress((void**)&wkh, g_wkh);
    cudaGetSymbolAddress((void**)&wkl, g_wkl);
    cudaGetSymbolAddress((void**)&wvh, g_wvh);
    cudaGetSymbolAddress((void**)&wvl, g_wvl);
    cudaGetSymbolAddress((void**)&woh, g_woh);
    cudaGetSymbolAddress((void**)&wol, g_wol);
    cudaGetSymbolAddress((void**)&qh, g_qh);
    cudaGetSymbolAddress((void**)&ql, g_ql);
    cudaGetSymbolAddress((void**)&kh, g_kh);
    cudaGetSymbolAddress((void**)&kl, g_kl);
    cudaGetSymbolAddress((void**)&vh, g_vh);
    cudaGetSymbolAddress((void**)&oh, g_oh);

    static cudaStream_t s2 = nullptr, s3 = nullptr, s4 = nullptr;
    static cudaEvent_t evFork = nullptr, evJoin = nullptr;
    static cudaEvent_t evConv = nullptr, evK = nullptr, evV = nullptr;
    static cudaEvent_t evQ = nullptr, evO2 = nullptr;
    if (s2 == nullptr) {
        cudaStreamCreateWithFlags(&s2, cudaStreamNonBlocking);
        cudaStreamCreateWithFlags(&s3, cudaStreamNonBlocking);
        cudaStreamCreateWithFlags(&s4, cudaStreamNonBlocking);
        cudaEventCreateWithFlags(&evFork, cudaEventDisableTiming);
        cudaEventCreateWithFlags(&evJoin, cudaEventDisableTiming);
        cudaEventCreateWithFlags(&evConv, cudaEventDisableTiming);
        cudaEventCreateWithFlags(&evK, cudaEventDisableTiming);
        cudaEventCreateWithFlags(&evV, cudaEventDisableTiming);
        cudaEventCreateWithFlags(&evQ, cudaEventDisableTiming);
        cudaEventCreateWithFlags(&evO2, cudaEventDisableTiming);
    }

    // ---- fork: pos_bias on side stream ----
    cudaEventRecord(evFork, 0);
    cudaStreamWaitEvent(s2, evFork, 0);
    {
        dim3 bg(S_LEN, NHEADS);
        bias_kernel<<<bg, 256, 0, s2>>>(tbl, out + OUT_ELEMS);
    }
    cudaEventRecord(evJoin, s2);

    // ---- conversions (main stream) ----
    conv_all<<<12288, 256>>>(X, xh, xl, Wq, wqh, wql, Wk, wkh, wkl,
                             Wv, wvh, wvl, Wo, woh, wol);
    cudaEventRecord(evConv, 0);
    cudaStreamWaitEvent(s3, evConv, 0);
    cudaStreamWaitEvent(s4, evConv, 0);

    dim3 gg(DMODEL / 128, M_ROWS / 128);      // (8, 64) = 512 CTAs

    cudaFuncSetAttribute(gemm_h<3, 1>, cudaFuncAttributeMaxDynamicSharedMemorySize,
                         2 * 4 * MATB);
    cudaFuncSetAttribute(gemm_h<1, 2>, cudaFuncAttributeMaxDynamicSharedMemorySize,
                         2 * 2 * MATB);
    cudaFuncSetAttribute(gemm_h<1, 0>, cudaFuncAttributeMaxDynamicSharedMemorySize,
                         2 * 2 * MATB);
    cudaFuncSetAttribute(flash_hmma, cudaFuncAttributeMaxDynamicSharedMemorySize,
                         FLASH_SMEM);

    // Q on main, K on s3, V on s4 — independent, tails overlap
    gemm_h<3, 1><<<gg, 128, 2 * 4 * MATB>>>(xh, xl, wqh, wql,
                                            nullptr, qh, ql,
                                            M_ROWS, DMODEL, DMODEL);
    cudaEventRecord(evQ, 0);
    gemm_h<3, 1><<<gg, 128, 2 * 4 * MATB, s3>>>(xh, xl, wkh, wkl,
                                                nullptr, kh, kl,
                                                M_ROWS, DMODEL, DMODEL);
    cudaEventRecord(evK, s3);
    gemm_h<1, 2><<<gg, 128, 2 * 2 * MATB, s4>>>(xh, nullptr, wvh, nullptr,
                                                nullptr, vh, nullptr,
                                                M_ROWS, DMODEL, DMODEL);
    cudaEventRecord(evV, s4);

    // flash half 1 (b=0,1) on main; flash half 2 (b=2,3) on s3
    cudaStreamWaitEvent(0, evK, 0);
    cudaStreamWaitEvent(0, evV, 0);
    cudaStreamWaitEvent(s3, evQ, 0);
    cudaStreamWaitEvent(s3, evV, 0);

    dim3 fgh(S_LEN / 128, NHEADS, BATCH / 2);
    flash_hmma<<<fgh, 256, FLASH_SMEM>>>(qh, ql, kh, kl, vh, tbl, oh, 0);
    flash_hmma<<<fgh, 256, FLASH_SMEM, s3>>>(qh, ql, kh, kl, vh, tbl, oh, 2);

    // O-projection split by M halves: O1 (rows of b=0,1) overlaps flash half 2
    dim3 ggh(DMODEL / 128, M_ROWS / 2 / 128);   // (8, 32) = 256 CTAs
    const int MH = M_ROWS / 2;
    gemm_h<1, 0><<<ggh, 128, 2 * 2 * MATB>>>(oh, nullptr, woh, nullptr,
                                             out, nullptr, nullptr,
                                             MH, DMODEL, DMODEL);
    gemm_h<1, 0><<<ggh, 128, 2 * 2 * MATB, s3>>>(oh + (size_t)MH * DMODEL, nullptr,
                                                 woh, nullptr,
                                                 out + (size_t)MH * DMODEL,
                                                 nullptr, nullptr,
                                                 MH, DMODEL, DMODEL);
    cudaEventRecord(evO2, s3);
    cudaStreamWaitEvent(0, evO2, 0);

    // ---- join: pos_bias must complete before kernel_launch's work is done ----
    cudaStreamWaitEvent(0, evJoin, 0);
}